// round 1
// baseline (speedup 1.0000x reference)
#include <cuda_runtime.h>
#include <math.h>

#define NTn     34000
#define NTYPES  3
#define NMP     2
#define ECNT    300000
#define HH      8
#define DD      64
#define HDIM    512
#define AVd     128
#define COUT    8
#define NTGTn   1000
#define NNODES  (NTYPES*NTn)

// ---------------- scratch (device globals; no allocation) ----------------
__device__ float g_h0[(size_t)NNODES*DD];        // layer-0 input features
__device__ float g_h1[(size_t)NNODES*DD];        // layer-1 input features
__device__ float g_e [(size_t)ECNT*HH];          // per-edge attention logits
__device__ float g_st0[(size_t)NTn*HDIM];        // per-metapath node outputs
__device__ float g_st1[(size_t)NTn*HDIM];
__device__ int   g_counts[NTYPES*NMP*NTn];
__device__ int   g_ofs   [NTYPES*NMP*(NTn+1)];
__device__ int   g_cursor[NTYPES*NMP*NTn];
__device__ int   g_order [NTYPES*NMP*ECNT];
__device__ float g_s[2];
__device__ float g_beta[2];

// ---------------- small utility kernels ----------------
__global__ void zero_i_kernel(int* p, int n) {
    int i = blockIdx.x*blockDim.x + threadIdx.x;
    if (i < n) p[i] = 0;
}

__global__ void zero_s_kernel() { g_s[0] = 0.f; g_s[1] = 0.f; }

__global__ void beta_kernel() {
    float s0 = g_s[0] * (1.f/(float)NTn);
    float s1 = g_s[1] * (1.f/(float)NTn);
    float m  = fmaxf(s0, s1);
    float e0 = expf(s0 - m), e1 = expf(s1 - m);
    float d  = e0 + e1;
    g_beta[0] = e0 / d;
    g_beta[1] = e1 / d;
}

// ---------------- CSR construction ----------------
__global__ void hist_kernel(const int* __restrict__ mp, int* __restrict__ counts, int ibase) {
    int e = blockIdx.x*blockDim.x + threadIdx.x;
    if (e < ECNT) atomicAdd(&counts[mp[e*3] - ibase], 1);
}

__global__ void scan_kernel(const int* __restrict__ counts,
                            int* __restrict__ ofs, int* __restrict__ cursor) {
    __shared__ int warp_sums[32];
    __shared__ int s_carry;
    if (threadIdx.x == 0) s_carry = 0;
    __syncthreads();
    int lane = threadIdx.x & 31, wid = threadIdx.x >> 5;
    for (int base = 0; base < NTn; base += 1024) {
        int idx = base + threadIdx.x;
        int v = (idx < NTn) ? counts[idx] : 0;
        int orig = v;
        #pragma unroll
        for (int d = 1; d < 32; d <<= 1) {
            int t = __shfl_up_sync(0xffffffffu, v, d);
            if (lane >= d) v += t;
        }
        if (lane == 31) warp_sums[wid] = v;
        __syncthreads();
        if (wid == 0) {
            int w = warp_sums[lane];
            #pragma unroll
            for (int d = 1; d < 32; d <<= 1) {
                int t = __shfl_up_sync(0xffffffffu, w, d);
                if (lane >= d) w += t;
            }
            warp_sums[lane] = w;
        }
        __syncthreads();
        int add  = s_carry + (wid > 0 ? warp_sums[wid-1] : 0);
        int excl = add + v - orig;
        if (idx < NTn) { ofs[idx] = excl; cursor[idx] = excl; }
        __syncthreads();
        if (threadIdx.x == 1023) s_carry = add + v;
        __syncthreads();
    }
    if (threadIdx.x == 0) ofs[NTn] = s_carry;
}

__global__ void scatter_kernel(const int* __restrict__ mp, int* __restrict__ cursor,
                               int* __restrict__ order, int ibase) {
    int e = blockIdx.x*blockDim.x + threadIdx.x;
    if (e < ECNT) {
        int dst = mp[e*3] - ibase;
        int pos = atomicAdd(&cursor[dst], 1);
        order[pos] = e;
    }
}

// ---------------- per-edge attention logits (warp per edge) ----------------
__global__ __launch_bounds__(256)
void edge_kernel(const float* __restrict__ h, const int* __restrict__ mp,
                 const float* __restrict__ a1, const float* __restrict__ a2) {
    __shared__ float a1s[HH][DD];
    __shared__ float a2s[HH][DD];
    for (int i = threadIdx.x; i < HH*DD; i += blockDim.x) {
        a1s[0][i] = a1[i];
        a2s[0][i] = a2[i];
    }
    __syncthreads();
    int lane = threadIdx.x & 31;
    int wid  = threadIdx.x >> 5;
    int e = blockIdx.x*8 + wid;
    if (e >= ECNT) return;

    int n0 = __ldg(&mp[e*3+0]);
    int n1 = __ldg(&mp[e*3+1]);
    int n2 = __ldg(&mp[e*3+2]);

    float f0a = h[(size_t)n0*DD + lane],      f0b = h[(size_t)n0*DD + 32 + lane];
    float f1a = h[(size_t)n1*DD + lane],      f1b = h[(size_t)n1*DD + 32 + lane];
    float f2a = h[(size_t)n2*DD + lane],      f2b = h[(size_t)n2*DD + 32 + lane];
    const float third = 1.f/3.f;
    float hid_a = (f0a + f1a + f2a) * third;
    float hid_b = (f0b + f1b + f2b) * third;

    float rv[HH];
    #pragma unroll
    for (int hh = 0; hh < HH; hh++) {
        float v = f0a*a1s[hh][lane] + f0b*a1s[hh][lane+32]
                + hid_a*a2s[hh][lane] + hid_b*a2s[hh][lane+32];
        #pragma unroll
        for (int o = 16; o > 0; o >>= 1) v += __shfl_xor_sync(0xffffffffu, v, o);
        rv[hh] = v;
    }
    float myv = 0.f;
    #pragma unroll
    for (int hh = 0; hh < HH; hh++) if (lane == hh) myv = rv[hh];
    if (lane < HH) {
        myv = (myv > 0.f) ? myv : 0.2f*myv;   // leaky_relu 0.2
        g_e[(size_t)e*HH + lane] = myv;
    }
}

// ---------------- segment softmax + weighted sum (warp per node) ----------------
__global__ __launch_bounds__(256)
void node_kernel(const float* __restrict__ h, const int* __restrict__ mp,
                 const int* __restrict__ ofs, const int* __restrict__ order,
                 float* __restrict__ st) {
    int lane = threadIdx.x & 31;
    int wid  = threadIdx.x >> 5;
    int n = blockIdx.x*8 + wid;
    if (n >= NTn) return;

    int s0 = ofs[n], s1 = ofs[n+1];

    // pass 1: per-head max
    float mh[HH];
    #pragma unroll
    for (int hh = 0; hh < HH; hh++) mh[hh] = -3.402823466e38f;
    for (int j = s0 + lane; j < s1; j += 32) {
        int eid = __ldg(&order[j]);
        #pragma unroll
        for (int hh = 0; hh < HH; hh++)
            mh[hh] = fmaxf(mh[hh], __ldg(&g_e[(size_t)eid*HH + hh]));
    }
    #pragma unroll
    for (int hh = 0; hh < HH; hh++) {
        #pragma unroll
        for (int o = 16; o > 0; o >>= 1)
            mh[hh] = fmaxf(mh[hh], __shfl_xor_sync(0xffffffffu, mh[hh], o));
    }
    float myM = 0.f;
    #pragma unroll
    for (int hh = 0; hh < HH; hh++) if (lane == hh) myM = mh[hh];

    // pass 2: accumulate num (per-lane dims d=lane, lane+32) and den (lanes 0..7)
    float den = 0.f;
    float acc[2*HH];
    #pragma unroll
    for (int k = 0; k < 2*HH; k++) acc[k] = 0.f;
    const float third = 1.f/3.f;
    for (int j = s0; j < s1; ++j) {
        int eid = __ldg(&order[j]);
        float exv = 0.f;
        if (lane < HH) exv = expf(__ldg(&g_e[(size_t)eid*HH + lane]) - myM);
        den += exv;
        int n0 = __ldg(&mp[eid*3+0]);
        int n1 = __ldg(&mp[eid*3+1]);
        int n2 = __ldg(&mp[eid*3+2]);
        float hv0 = (h[(size_t)n0*DD+lane]    + h[(size_t)n1*DD+lane]    + h[(size_t)n2*DD+lane])    * third;
        float hv1 = (h[(size_t)n0*DD+32+lane] + h[(size_t)n1*DD+32+lane] + h[(size_t)n2*DD+32+lane]) * third;
        #pragma unroll
        for (int hh = 0; hh < HH; hh++) {
            float exh = __shfl_sync(0xffffffffu, exv, hh);
            acc[hh*2+0] += exh * hv0;
            acc[hh*2+1] += exh * hv1;
        }
    }
    #pragma unroll
    for (int hh = 0; hh < HH; hh++) {
        float dh = __shfl_sync(0xffffffffu, den, hh);
        float inv = 1.f / fmaxf(dh, 1e-9f);
        float v0 = acc[hh*2+0] * inv;
        float v1 = acc[hh*2+1] * inv;
        v0 = (v0 > 0.f) ? v0 : (expf(v0) - 1.f);  // elu
        v1 = (v1 > 0.f) ? v1 : (expf(v1) - 1.f);
        st[(size_t)n*HDIM + hh*DD + lane]      = v0;
        st[(size_t)n*HDIM + hh*DD + 32 + lane] = v1;
    }
}

// ---------------- tiled SGEMM with fused epilogues ----------------
// MODE 0: C = A0 @ B + bias
// MODE 1: atomicAdd(sOut, sum_rows( tanh(A0@B + bias) . q ))   (no C store)
// MODE 2: C = elu( (beta0*A0 + beta1*A1) @ B + bias )
template<int BM, int BN, int BK, int TM, int TN, int MODE>
__global__ __launch_bounds__((BM/TM)*(BN/TN))
void gemm_kernel(int M, int K, int N,
                 const float* __restrict__ A0, const float* __restrict__ A1,
                 const float* __restrict__ betaPtr,
                 const float* __restrict__ B,  const float* __restrict__ bias,
                 float* __restrict__ C, const float* __restrict__ q,
                 float* __restrict__ sOut) {
    constexpr int THREADS = (BM/TM)*(BN/TN);
    __shared__ float As[BK][BM];
    __shared__ float Bs[BK][BN];
    const int tid = threadIdx.x;
    const int tx  = tid % (BN/TN);
    const int ty  = tid / (BN/TN);
    const int mBase = blockIdx.y * BM;
    const int nBase = blockIdx.x * BN;

    float acc[TM][TN];
    #pragma unroll
    for (int i = 0; i < TM; i++)
        #pragma unroll
        for (int j = 0; j < TN; j++) acc[i][j] = 0.f;

    float cb0 = 0.f, cb1 = 0.f;
    if (MODE == 2) { cb0 = betaPtr[0]; cb1 = betaPtr[1]; }

    for (int k0 = 0; k0 < K; k0 += BK) {
        #pragma unroll
        for (int t = tid; t < BM*BK/4; t += THREADS) {
            int row = t / (BK/4);
            int kq  = t % (BK/4);
            int gr  = mBase + row;
            float4 v = make_float4(0.f, 0.f, 0.f, 0.f);
            if (gr < M) {
                v = *(const float4*)(A0 + (size_t)gr*K + k0 + kq*4);
                if (MODE == 2) {
                    float4 w = *(const float4*)(A1 + (size_t)gr*K + k0 + kq*4);
                    v.x = cb0*v.x + cb1*w.x;
                    v.y = cb0*v.y + cb1*w.y;
                    v.z = cb0*v.z + cb1*w.z;
                    v.w = cb0*v.w + cb1*w.w;
                }
            }
            As[kq*4+0][row] = v.x;
            As[kq*4+1][row] = v.y;
            As[kq*4+2][row] = v.z;
            As[kq*4+3][row] = v.w;
        }
        #pragma unroll
        for (int t = tid; t < BK*BN/4; t += THREADS) {
            int kk = t / (BN/4);
            int nq = t % (BN/4);
            *(float4*)&Bs[kk][nq*4] = *(const float4*)(B + (size_t)(k0+kk)*N + nBase + nq*4);
        }
        __syncthreads();
        #pragma unroll
        for (int kk = 0; kk < BK; kk++) {
            float af[TM], bf[TN];
            #pragma unroll
            for (int i = 0; i < TM; i++) af[i] = As[kk][ty*TM + i];
            #pragma unroll
            for (int j = 0; j < TN; j++) bf[j] = Bs[kk][tx*TN + j];
            #pragma unroll
            for (int i = 0; i < TM; i++)
                #pragma unroll
                for (int j = 0; j < TN; j++) acc[i][j] += af[i]*bf[j];
        }
        __syncthreads();
    }

    if (MODE == 1) {
        float local = 0.f;
        #pragma unroll
        for (int i = 0; i < TM; i++) {
            int gr = mBase + ty*TM + i;
            if (gr < M) {
                #pragma unroll
                for (int j = 0; j < TN; j++) {
                    int col = nBase + tx*TN + j;
                    local += tanhf(acc[i][j] + bias[col]) * q[col];
                }
            }
        }
        __shared__ float red[THREADS];
        red[tid] = local;
        __syncthreads();
        #pragma unroll
        for (int s2 = THREADS/2; s2 > 0; s2 >>= 1) {
            if (tid < s2) red[tid] += red[tid + s2];
            __syncthreads();
        }
        if (tid == 0) atomicAdd(sOut, red[0]);
    } else {
        #pragma unroll
        for (int i = 0; i < TM; i++) {
            int gr = mBase + ty*TM + i;
            if (gr < M) {
                #pragma unroll
                for (int j = 0; j < TN; j++) {
                    int col = nBase + tx*TN + j;
                    float v = acc[i][j] + bias[col];
                    if (MODE == 2) v = (v > 0.f) ? v : (expf(v) - 1.f);
                    C[(size_t)gr*N + col] = v;
                }
            }
        }
    }
}

// ---------------- final logits at target rows ----------------
__global__ __launch_bounds__(256)
void final_kernel(const float* __restrict__ st0, const float* __restrict__ st1,
                  const float* __restrict__ betaPtr,
                  const float* __restrict__ lW1, const float* __restrict__ lb1,
                  const int* __restrict__ tgt, float* __restrict__ out) {
    int t    = blockIdx.x;
    int col  = threadIdx.x >> 5;   // 8 warps = 8 output cols
    int lane = threadIdx.x & 31;
    int n = tgt[t];
    float b0 = betaPtr[0], b1 = betaPtr[1];
    float acc = 0.f;
    for (int k = lane; k < HDIM; k += 32) {
        float a = b0*st0[(size_t)n*HDIM + k] + b1*st1[(size_t)n*HDIM + k];
        acc += a * lW1[(size_t)k*COUT + col];
    }
    #pragma unroll
    for (int o = 16; o > 0; o >>= 1) acc += __shfl_xor_sync(0xffffffffu, acc, o);
    if (lane == 0) out[(size_t)t*COUT + col] = acc + lb1[col];
}

// ---------------- host orchestration ----------------
extern "C" void kernel_launch(void* const* d_in, const int* in_sizes, int n_in,
                              void* d_out, int out_size) {
    const float* X0   = (const float*)d_in[0];
    const float* X1   = (const float*)d_in[1];
    const float* X2   = (const float*)d_in[2];
    const float* fcW[3] = {(const float*)d_in[3], (const float*)d_in[5], (const float*)d_in[7]};
    const float* fcb[3] = {(const float*)d_in[4], (const float*)d_in[6], (const float*)d_in[8]};
    const float* attn1 = (const float*)d_in[9];
    const float* attn2 = (const float*)d_in[10];
    const float* mpW   = (const float*)d_in[11];
    const float* mpb   = (const float*)d_in[12];
    const float* mpq   = (const float*)d_in[13];
    const float* lW0   = (const float*)d_in[14];
    const float* lb0   = (const float*)d_in[15];
    const float* lW1   = (const float*)d_in[16];
    const float* lb1   = (const float*)d_in[17];
    const int*   mpidx = (const int*)d_in[18];
    const int*   tgt   = (const int*)d_in[19];
    float* out = (float*)d_out;

    float *h0, *h1, *stp[2], *sp, *bp;
    int *cnt, *ofs, *cur, *ord;
    cudaGetSymbolAddress((void**)&h0,     g_h0);
    cudaGetSymbolAddress((void**)&h1,     g_h1);
    cudaGetSymbolAddress((void**)&stp[0], g_st0);
    cudaGetSymbolAddress((void**)&stp[1], g_st1);
    cudaGetSymbolAddress((void**)&sp,     g_s);
    cudaGetSymbolAddress((void**)&bp,     g_beta);
    cudaGetSymbolAddress((void**)&cnt,    g_counts);
    cudaGetSymbolAddress((void**)&ofs,    g_ofs);
    cudaGetSymbolAddress((void**)&cur,    g_cursor);
    cudaGetSymbolAddress((void**)&ord,    g_order);

    const int mTiles = (NTn + 127) / 128;

    // 1) per-type feature FC -> h0
    const float* Xs[3] = {X0, X1, X2};
    const int    Ks[3] = {512, 256, 128};
    for (int i = 0; i < NTYPES; i++) {
        gemm_kernel<128,64,16,8,4,0><<<dim3(1, mTiles), 256>>>(
            NTn, Ks[i], DD, Xs[i], nullptr, nullptr,
            fcW[i], fcb[i], h0 + (size_t)i*NTn*DD, nullptr, nullptr);
    }

    // 2) CSR per (type, metapath) — layer-invariant, built once
    {
        int total = NTYPES*NMP*NTn;
        zero_i_kernel<<<(total + 255)/256, 256>>>(cnt, total);
        for (int i = 0; i < NTYPES; i++) {
            for (int p = 0; p < NMP; p++) {
                int slab = i*NMP + p;
                const int* mp = mpidx + (size_t)slab*ECNT*3;
                hist_kernel<<<(ECNT + 255)/256, 256>>>(mp, cnt + (size_t)slab*NTn, i*NTn);
                scan_kernel<<<1, 1024>>>(cnt + (size_t)slab*NTn,
                                         ofs + (size_t)slab*(NTn+1),
                                         cur + (size_t)slab*NTn);
                scatter_kernel<<<(ECNT + 255)/256, 256>>>(mp, cur + (size_t)slab*NTn,
                                                          ord + (size_t)slab*ECNT, i*NTn);
            }
        }
    }

    // 3) layers
    for (int l = 0; l < 2; l++) {
        const float* hin = (l == 0) ? h0 : h1;
        int tcount = (l == 0) ? NTYPES : 1;  // layer 1: only type 0 feeds targets
        for (int i = 0; i < tcount; i++) {
            for (int p = 0; p < NMP; p++) {
                int slab = i*NMP + p;
                const int* mp = mpidx + (size_t)slab*ECNT*3;
                const float* a1 = attn1 + (size_t)((l*NTYPES + i)*NMP + p)*HH*DD;
                const float* a2 = attn2 + (size_t)((l*NTYPES + i)*NMP + p)*HH*DD;
                edge_kernel<<<(ECNT + 7)/8, 256>>>(hin, mp, a1, a2);
                node_kernel<<<(NTn + 7)/8, 256>>>(hin, mp,
                                                  ofs + (size_t)slab*(NTn+1),
                                                  ord + (size_t)slab*ECNT, stp[p]);
            }
            zero_s_kernel<<<1, 1>>>();
            for (int p = 0; p < NMP; p++) {
                gemm_kernel<128,128,16,8,8,1><<<dim3(1, mTiles), 256>>>(
                    NTn, HDIM, AVd, stp[p], nullptr, nullptr,
                    mpW + (size_t)(l*NTYPES + i)*HDIM*AVd,
                    mpb + (size_t)(l*NTYPES + i)*AVd,
                    nullptr,
                    mpq + (size_t)(l*NTYPES + i)*AVd,
                    sp + p);
            }
            beta_kernel<<<1, 1>>>();
            if (l == 0) {
                gemm_kernel<128,64,16,8,4,2><<<dim3(1, mTiles), 256>>>(
                    NTn, HDIM, DD, stp[0], stp[1], bp,
                    lW0, lb0, h1 + (size_t)i*NTn*DD, nullptr, nullptr);
            } else {
                final_kernel<<<NTGTn, 256>>>(stp[0], stp[1], bp, lW1, lb1, tgt, out);
            }
        }
    }
}

// round 2
// speedup vs baseline: 1.1419x; 1.1419x over previous
#include <cuda_runtime.h>
#include <math.h>

#define NTn     34000
#define NTYPES  3
#define NMP     2
#define ECNT    300000
#define HH      8
#define DD      64
#define HDIM    512
#define AVd     128
#define COUT    8
#define NTGTn   1000
#define NNODES  (NTYPES*NTn)
#define NSLAB   (NTYPES*NMP)

typedef unsigned long long u64;

// ---------------- scratch (device globals; no allocation) ----------------
__device__ float g_h0[(size_t)NNODES*DD];
__device__ float g_h1[(size_t)NNODES*DD];
__device__ float g_e [(size_t)NSLAB*ECNT*HH];
__device__ float g_st[(size_t)NSLAB*NTn*HDIM];
__device__ int   g_counts[NSLAB*NTn];
__device__ int   g_ofs   [NSLAB*(NTn+1)];
__device__ int   g_cursor[NSLAB*NTn];
__device__ int   g_order [NSLAB*ECNT];
__device__ float g_s[NSLAB];
__device__ float g_beta[NSLAB];

// ---------------- f32x2 packed helpers ----------------
__device__ __forceinline__ u64 pack2(float x, float y) {
    u64 r; asm("mov.b64 %0, {%1, %2};" : "=l"(r) : "f"(x), "f"(y)); return r;
}
__device__ __forceinline__ void ffma2(u64& d, u64 a, u64 b) {
    asm("fma.rn.f32x2 %0, %1, %2, %0;" : "+l"(d) : "l"(a), "l"(b));
}
__device__ __forceinline__ float2 unpack2(u64 v) {
    float x, y; asm("mov.b64 {%0, %1}, %2;" : "=f"(x), "=f"(y) : "l"(v));
    return make_float2(x, y);
}

// ---------------- small utility kernels ----------------
__global__ void zero_i_kernel(int* p, int n) {
    int i = blockIdx.x*blockDim.x + threadIdx.x;
    if (i < n) p[i] = 0;
}
__global__ void zero_s_kernel() {
    if (threadIdx.x < NSLAB) g_s[threadIdx.x] = 0.f;
}
__global__ void beta_kernel(int ntypes) {
    int t = threadIdx.x;
    if (t < ntypes) {
        float s0 = g_s[t*2+0] * (1.f/(float)NTn);
        float s1 = g_s[t*2+1] * (1.f/(float)NTn);
        float m  = fmaxf(s0, s1);
        float e0 = expf(s0 - m), e1 = expf(s1 - m);
        float d  = e0 + e1;
        g_beta[t*2+0] = e0 / d;
        g_beta[t*2+1] = e1 / d;
    }
}

// ---------------- CSR construction (batched over slabs via z) ----------------
__global__ void hist_kernel(const int* __restrict__ mpidx, int* __restrict__ counts) {
    int slab = blockIdx.z;
    int e = blockIdx.x*blockDim.x + threadIdx.x;
    if (e < ECNT) {
        int dst = mpidx[(size_t)slab*ECNT*3 + e*3] - (slab/NMP)*NTn;
        atomicAdd(&counts[(size_t)slab*NTn + dst], 1);
    }
}

__global__ void scan_kernel(const int* __restrict__ countsAll,
                            int* __restrict__ ofsAll, int* __restrict__ cursorAll) {
    int slab = blockIdx.x;
    const int* counts = countsAll + (size_t)slab*NTn;
    int* ofs    = ofsAll    + (size_t)slab*(NTn+1);
    int* cursor = cursorAll + (size_t)slab*NTn;
    __shared__ int warp_sums[32];
    __shared__ int s_carry;
    if (threadIdx.x == 0) s_carry = 0;
    __syncthreads();
    int lane = threadIdx.x & 31, wid = threadIdx.x >> 5;
    for (int base = 0; base < NTn; base += 1024) {
        int idx = base + threadIdx.x;
        int v = (idx < NTn) ? counts[idx] : 0;
        int orig = v;
        #pragma unroll
        for (int d = 1; d < 32; d <<= 1) {
            int t = __shfl_up_sync(0xffffffffu, v, d);
            if (lane >= d) v += t;
        }
        if (lane == 31) warp_sums[wid] = v;
        __syncthreads();
        if (wid == 0) {
            int w = warp_sums[lane];
            #pragma unroll
            for (int d = 1; d < 32; d <<= 1) {
                int t = __shfl_up_sync(0xffffffffu, w, d);
                if (lane >= d) w += t;
            }
            warp_sums[lane] = w;
        }
        __syncthreads();
        int add  = s_carry + (wid > 0 ? warp_sums[wid-1] : 0);
        int excl = add + v - orig;
        if (idx < NTn) { ofs[idx] = excl; cursor[idx] = excl; }
        __syncthreads();
        if (threadIdx.x == 1023) s_carry = add + v;
        __syncthreads();
    }
    if (threadIdx.x == 0) ofs[NTn] = s_carry;
}

__global__ void scatter_kernel(const int* __restrict__ mpidx, int* __restrict__ cursorAll,
                               int* __restrict__ orderAll) {
    int slab = blockIdx.z;
    int e = blockIdx.x*blockDim.x + threadIdx.x;
    if (e < ECNT) {
        int dst = mpidx[(size_t)slab*ECNT*3 + e*3] - (slab/NMP)*NTn;
        int pos = atomicAdd(&cursorAll[(size_t)slab*NTn + dst], 1);
        orderAll[(size_t)slab*ECNT + pos] = e;
    }
}

// ---------------- per-edge attention logits (warp per edge; z = slab) ----------------
__global__ __launch_bounds__(256)
void edge_kernel(const float* __restrict__ h, const int* __restrict__ mpidx,
                 const float* __restrict__ attn1, const float* __restrict__ attn2,
                 int layer) {
    int slab = blockIdx.z;
    const int*   mp = mpidx + (size_t)slab*ECNT*3;
    const float* a1 = attn1 + (size_t)(layer*NSLAB + slab)*HH*DD;
    const float* a2 = attn2 + (size_t)(layer*NSLAB + slab)*HH*DD;
    float* eOut = g_e + (size_t)slab*ECNT*HH;

    __shared__ float a1s[HH][DD];
    __shared__ float a2s[HH][DD];
    for (int i = threadIdx.x; i < HH*DD; i += blockDim.x) {
        a1s[0][i] = a1[i];
        a2s[0][i] = a2[i];
    }
    __syncthreads();
    int lane = threadIdx.x & 31;
    int wid  = threadIdx.x >> 5;
    int e = blockIdx.x*8 + wid;
    if (e >= ECNT) return;

    int n0 = __ldg(&mp[e*3+0]);
    int n1 = __ldg(&mp[e*3+1]);
    int n2 = __ldg(&mp[e*3+2]);

    float f0a = h[(size_t)n0*DD + lane],      f0b = h[(size_t)n0*DD + 32 + lane];
    float f1a = h[(size_t)n1*DD + lane],      f1b = h[(size_t)n1*DD + 32 + lane];
    float f2a = h[(size_t)n2*DD + lane],      f2b = h[(size_t)n2*DD + 32 + lane];
    const float third = 1.f/3.f;
    float hid_a = (f0a + f1a + f2a) * third;
    float hid_b = (f0b + f1b + f2b) * third;

    float rv[HH];
    #pragma unroll
    for (int hh = 0; hh < HH; hh++) {
        float v = f0a*a1s[hh][lane] + f0b*a1s[hh][lane+32]
                + hid_a*a2s[hh][lane] + hid_b*a2s[hh][lane+32];
        #pragma unroll
        for (int o = 16; o > 0; o >>= 1) v += __shfl_xor_sync(0xffffffffu, v, o);
        rv[hh] = v;
    }
    float myv = 0.f;
    #pragma unroll
    for (int hh = 0; hh < HH; hh++) if (lane == hh) myv = rv[hh];
    if (lane < HH) {
        myv = (myv > 0.f) ? myv : 0.2f*myv;   // leaky_relu 0.2
        eOut[(size_t)e*HH + lane] = myv;
    }
}

// ---------------- segment softmax + weighted sum (warp per node; z = slab) ----------------
__global__ __launch_bounds__(256)
void node_kernel(const float* __restrict__ h, const int* __restrict__ mpidx) {
    int slab = blockIdx.z;
    const int*   mp    = mpidx   + (size_t)slab*ECNT*3;
    const int*   ofs   = g_ofs   + (size_t)slab*(NTn+1);
    const int*   order = g_order + (size_t)slab*ECNT;
    const float* eIn   = g_e     + (size_t)slab*ECNT*HH;
    float*       st    = g_st    + (size_t)slab*NTn*HDIM;

    int lane = threadIdx.x & 31;
    int wid  = threadIdx.x >> 5;
    int n = blockIdx.x*8 + wid;
    if (n >= NTn) return;

    int s0 = ofs[n], s1 = ofs[n+1];

    // pass 1: per-head max
    float mh[HH];
    #pragma unroll
    for (int hh = 0; hh < HH; hh++) mh[hh] = -3.402823466e38f;
    for (int j = s0 + lane; j < s1; j += 32) {
        int eid = __ldg(&order[j]);
        #pragma unroll
        for (int hh = 0; hh < HH; hh++)
            mh[hh] = fmaxf(mh[hh], __ldg(&eIn[(size_t)eid*HH + hh]));
    }
    #pragma unroll
    for (int hh = 0; hh < HH; hh++) {
        #pragma unroll
        for (int o = 16; o > 0; o >>= 1)
            mh[hh] = fmaxf(mh[hh], __shfl_xor_sync(0xffffffffu, mh[hh], o));
    }
    float myM = 0.f;
    #pragma unroll
    for (int hh = 0; hh < HH; hh++) if (lane == hh) myM = mh[hh];

    // pass 2: accumulate numerator (dims lane, lane+32) and denominator (lanes 0..7)
    float den = 0.f;
    float acc[2*HH];
    #pragma unroll
    for (int k = 0; k < 2*HH; k++) acc[k] = 0.f;
    const float third = 1.f/3.f;
    for (int j = s0; j < s1; ++j) {
        int eid = __ldg(&order[j]);
        float exv = 0.f;
        if (lane < HH) exv = expf(__ldg(&eIn[(size_t)eid*HH + lane]) - myM);
        den += exv;
        int n0 = __ldg(&mp[eid*3+0]);
        int n1 = __ldg(&mp[eid*3+1]);
        int n2 = __ldg(&mp[eid*3+2]);
        float hv0 = (h[(size_t)n0*DD+lane]    + h[(size_t)n1*DD+lane]    + h[(size_t)n2*DD+lane])    * third;
        float hv1 = (h[(size_t)n0*DD+32+lane] + h[(size_t)n1*DD+32+lane] + h[(size_t)n2*DD+32+lane]) * third;
        #pragma unroll
        for (int hh = 0; hh < HH; hh++) {
            float exh = __shfl_sync(0xffffffffu, exv, hh);
            acc[hh*2+0] += exh * hv0;
            acc[hh*2+1] += exh * hv1;
        }
    }
    #pragma unroll
    for (int hh = 0; hh < HH; hh++) {
        float dh = __shfl_sync(0xffffffffu, den, hh);
        float inv = 1.f / fmaxf(dh, 1e-9f);
        float v0 = acc[hh*2+0] * inv;
        float v1 = acc[hh*2+1] * inv;
        v0 = (v0 > 0.f) ? v0 : (expf(v0) - 1.f);  // elu
        v1 = (v1 > 0.f) ? v1 : (expf(v1) - 1.f);
        st[(size_t)n*HDIM + hh*DD + lane]      = v0;
        st[(size_t)n*HDIM + hh*DD + 32 + lane] = v1;
    }
}

// ---------------- tiled SGEMM (f32x2 packed FMA) with fused epilogues ----------------
// MODE 0: C = A0 @ B + bias
// MODE 1: atomicAdd(sOut, sum_rows( tanh(A0@B + bias) . q ))   (no C store)
// MODE 2: C = elu( (beta0*A0 + beta1*A1) @ B + bias )
struct GArgs {
    const float* A0; const float* A1;
    const float* B;  const float* bias;
    const float* q;  const float* beta2;
    float* C; float* sOut; int K;
};
struct GArgsN { GArgs z[NSLAB]; };

template<int BM, int BN, int BK, int TM, int TN, int MODE>
__global__ __launch_bounds__((BM/TM)*(BN/TN))
void gemm_kernel(int M, int N, GArgsN ga) {
    constexpr int THREADS = (BM/TM)*(BN/TN);
    const GArgs g = ga.z[blockIdx.z];
    __shared__ __align__(16) float As[BK][BM];
    __shared__ __align__(16) float Bs[BK][BN];
    const int tid = threadIdx.x;
    const int tx  = tid % (BN/TN);
    const int ty  = tid / (BN/TN);
    const int mBase = blockIdx.y * BM;
    const int nBase = blockIdx.x * BN;
    const int K = g.K;

    u64 acc2[TM/2][TN];
    #pragma unroll
    for (int u = 0; u < TM/2; u++)
        #pragma unroll
        for (int j = 0; j < TN; j++) acc2[u][j] = 0ull;

    float cb0 = 0.f, cb1 = 0.f;
    if (MODE == 2) { cb0 = g.beta2[0]; cb1 = g.beta2[1]; }

    for (int k0 = 0; k0 < K; k0 += BK) {
        #pragma unroll
        for (int t = tid; t < BM*BK/4; t += THREADS) {
            int row = t / (BK/4);
            int kq  = t % (BK/4);
            int gr  = mBase + row;
            float4 v = make_float4(0.f, 0.f, 0.f, 0.f);
            if (gr < M) {
                v = *(const float4*)(g.A0 + (size_t)gr*K + k0 + kq*4);
                if (MODE == 2) {
                    float4 w = *(const float4*)(g.A1 + (size_t)gr*K + k0 + kq*4);
                    v.x = cb0*v.x + cb1*w.x;
                    v.y = cb0*v.y + cb1*w.y;
                    v.z = cb0*v.z + cb1*w.z;
                    v.w = cb0*v.w + cb1*w.w;
                }
            }
            As[kq*4+0][row] = v.x;
            As[kq*4+1][row] = v.y;
            As[kq*4+2][row] = v.z;
            As[kq*4+3][row] = v.w;
        }
        #pragma unroll
        for (int t = tid; t < BK*BN/4; t += THREADS) {
            int kk = t / (BN/4);
            int nq = t % (BN/4);
            *(float4*)&Bs[kk][nq*4] = *(const float4*)(g.B + (size_t)(k0+kk)*N + nBase + nq*4);
        }
        __syncthreads();
        #pragma unroll
        for (int kk = 0; kk < BK; kk++) {
            u64 a2[TM/2];
            #pragma unroll
            for (int u = 0; u < TM/2; u++)
                a2[u] = *(const u64*)&As[kk][ty*TM + 2*u];
            float bf[TN];
            #pragma unroll
            for (int jq = 0; jq < TN/4; jq++) {
                float4 bv = *(const float4*)&Bs[kk][tx*TN + jq*4];
                bf[jq*4+0] = bv.x; bf[jq*4+1] = bv.y;
                bf[jq*4+2] = bv.z; bf[jq*4+3] = bv.w;
            }
            #pragma unroll
            for (int j = 0; j < TN; j++) {
                u64 bb = pack2(bf[j], bf[j]);
                #pragma unroll
                for (int u = 0; u < TM/2; u++)
                    ffma2(acc2[u][j], a2[u], bb);
            }
        }
        __syncthreads();
    }

    if (MODE == 1) {
        float local = 0.f;
        #pragma unroll
        for (int u = 0; u < TM/2; u++) {
            int gr0 = mBase + ty*TM + 2*u;
            int gr1 = gr0 + 1;
            #pragma unroll
            for (int j = 0; j < TN; j++) {
                int col = nBase + tx*TN + j;
                float2 v = unpack2(acc2[u][j]);
                float bq = g.q[col];
                float bb = g.bias[col];
                if (gr0 < M) local += tanhf(v.x + bb) * bq;
                if (gr1 < M) local += tanhf(v.y + bb) * bq;
            }
        }
        __shared__ float red[THREADS];
        red[tid] = local;
        __syncthreads();
        #pragma unroll
        for (int s2 = THREADS/2; s2 > 0; s2 >>= 1) {
            if (tid < s2) red[tid] += red[tid + s2];
            __syncthreads();
        }
        if (tid == 0) atomicAdd(g.sOut, red[0]);
    } else {
        #pragma unroll
        for (int u = 0; u < TM/2; u++) {
            int gr0 = mBase + ty*TM + 2*u;
            int gr1 = gr0 + 1;
            #pragma unroll
            for (int j = 0; j < TN; j++) {
                int col = nBase + tx*TN + j;
                float2 v = unpack2(acc2[u][j]);
                float bb = g.bias[col];
                float x = v.x + bb, y = v.y + bb;
                if (MODE == 2) {
                    x = (x > 0.f) ? x : (expf(x) - 1.f);
                    y = (y > 0.f) ? y : (expf(y) - 1.f);
                }
                if (gr0 < M) g.C[(size_t)gr0*N + col] = x;
                if (gr1 < M) g.C[(size_t)gr1*N + col] = y;
            }
        }
    }
}

// ---------------- final logits at target rows ----------------
__global__ __launch_bounds__(256)
void final_kernel(const float* __restrict__ st0, const float* __restrict__ st1,
                  const float* __restrict__ betaPtr,
                  const float* __restrict__ lW1, const float* __restrict__ lb1,
                  const int* __restrict__ tgt, float* __restrict__ out) {
    int t    = blockIdx.x;
    int col  = threadIdx.x >> 5;   // 8 warps = 8 output cols
    int lane = threadIdx.x & 31;
    int n = tgt[t];
    float b0 = betaPtr[0], b1 = betaPtr[1];
    float acc = 0.f;
    for (int k = lane; k < HDIM; k += 32) {
        float a = b0*st0[(size_t)n*HDIM + k] + b1*st1[(size_t)n*HDIM + k];
        acc += a * lW1[(size_t)k*COUT + col];
    }
    #pragma unroll
    for (int o = 16; o > 0; o >>= 1) acc += __shfl_xor_sync(0xffffffffu, acc, o);
    if (lane == 0) out[(size_t)t*COUT + col] = acc + lb1[col];
}

// ---------------- host orchestration ----------------
extern "C" void kernel_launch(void* const* d_in, const int* in_sizes, int n_in,
                              void* d_out, int out_size) {
    const float* X0   = (const float*)d_in[0];
    const float* X1   = (const float*)d_in[1];
    const float* X2   = (const float*)d_in[2];
    const float* fcW[3] = {(const float*)d_in[3], (const float*)d_in[5], (const float*)d_in[7]};
    const float* fcb[3] = {(const float*)d_in[4], (const float*)d_in[6], (const float*)d_in[8]};
    const float* attn1 = (const float*)d_in[9];
    const float* attn2 = (const float*)d_in[10];
    const float* mpW   = (const float*)d_in[11];
    const float* mpb   = (const float*)d_in[12];
    const float* mpq   = (const float*)d_in[13];
    const float* lW0   = (const float*)d_in[14];
    const float* lb0   = (const float*)d_in[15];
    const float* lW1   = (const float*)d_in[16];
    const float* lb1   = (const float*)d_in[17];
    const int*   mpidx = (const int*)d_in[18];
    const int*   tgt   = (const int*)d_in[19];
    float* out = (float*)d_out;

    float *h0, *h1, *stb, *sp, *bp;
    int *cnt, *ofs, *cur, *ord;
    cudaGetSymbolAddress((void**)&h0,  g_h0);
    cudaGetSymbolAddress((void**)&h1,  g_h1);
    cudaGetSymbolAddress((void**)&stb, g_st);
    cudaGetSymbolAddress((void**)&sp,  g_s);
    cudaGetSymbolAddress((void**)&bp,  g_beta);
    cudaGetSymbolAddress((void**)&cnt, g_counts);
    cudaGetSymbolAddress((void**)&ofs, g_ofs);
    cudaGetSymbolAddress((void**)&cur, g_cursor);
    cudaGetSymbolAddress((void**)&ord, g_order);

    const size_t SLABST = (size_t)NTn*HDIM;
    const int mTiles = (NTn + 127) / 128;

    // 1) zero histogram counts
    zero_i_kernel<<<(NSLAB*NTn + 255)/256, 256>>>(cnt, NSLAB*NTn);

    // 2) per-type feature FC -> h0 (batched z=3)
    {
        GArgsN ga = {};
        const float* Xs[3] = {X0, X1, X2};
        const int    Ks[3] = {512, 256, 128};
        for (int i = 0; i < NTYPES; i++) {
            ga.z[i].A0 = Xs[i]; ga.z[i].B = fcW[i]; ga.z[i].bias = fcb[i];
            ga.z[i].C  = h0 + (size_t)i*NTn*DD; ga.z[i].K = Ks[i];
        }
        gemm_kernel<128,64,16,8,4,0><<<dim3(1, mTiles, NTYPES), 256>>>(NTn, DD, ga);
    }

    // 3-5) CSR build (batched; layer-invariant)
    hist_kernel   <<<dim3((ECNT+255)/256, 1, NSLAB), 256>>>(mpidx, cnt);
    scan_kernel   <<<NSLAB, 1024>>>(cnt, ofs, cur);
    scatter_kernel<<<dim3((ECNT+255)/256, 1, NSLAB), 256>>>(mpidx, cur, ord);

    // ---- layer 0 (all 3 types, batched over 6 slabs) ----
    edge_kernel<<<dim3((ECNT+7)/8, 1, NSLAB), 256>>>(h0, mpidx, attn1, attn2, 0);
    node_kernel<<<dim3((NTn+7)/8, 1, NSLAB), 256>>>(h0, mpidx);
    zero_s_kernel<<<1, 32>>>();
    {
        GArgsN ga = {};
        for (int zz = 0; zz < NSLAB; zz++) {
            int type = zz / NMP;
            ga.z[zz].A0   = stb + (size_t)zz*SLABST;
            ga.z[zz].B    = mpW + (size_t)type*HDIM*AVd;
            ga.z[zz].bias = mpb + (size_t)type*AVd;
            ga.z[zz].q    = mpq + (size_t)type*AVd;
            ga.z[zz].sOut = sp + zz;
            ga.z[zz].K    = HDIM;
        }
        gemm_kernel<128,128,16,8,8,1><<<dim3(1, mTiles, NSLAB), 256>>>(NTn, AVd, ga);
    }
    beta_kernel<<<1, 32>>>(NTYPES);
    {
        GArgsN ga = {};
        for (int t = 0; t < NTYPES; t++) {
            ga.z[t].A0 = stb + (size_t)(t*2+0)*SLABST;
            ga.z[t].A1 = stb + (size_t)(t*2+1)*SLABST;
            ga.z[t].beta2 = bp + t*2;
            ga.z[t].B = lW0; ga.z[t].bias = lb0;
            ga.z[t].C = h1 + (size_t)t*NTn*DD;
            ga.z[t].K = HDIM;
        }
        gemm_kernel<128,64,16,8,4,2><<<dim3(1, mTiles, NTYPES), 256>>>(NTn, DD, ga);
    }

    // ---- layer 1 (only type 0 feeds target_idx) ----
    edge_kernel<<<dim3((ECNT+7)/8, 1, NMP), 256>>>(h1, mpidx, attn1, attn2, 1);
    node_kernel<<<dim3((NTn+7)/8, 1, NMP), 256>>>(h1, mpidx);
    zero_s_kernel<<<1, 32>>>();
    {
        GArgsN ga = {};
        for (int zz = 0; zz < NMP; zz++) {
            ga.z[zz].A0   = stb + (size_t)zz*SLABST;
            ga.z[zz].B    = mpW + (size_t)(NTYPES + 0)*HDIM*AVd;
            ga.z[zz].bias = mpb + (size_t)(NTYPES + 0)*AVd;
            ga.z[zz].q    = mpq + (size_t)(NTYPES + 0)*AVd;
            ga.z[zz].sOut = sp + zz;
            ga.z[zz].K    = HDIM;
        }
        gemm_kernel<128,128,16,8,8,1><<<dim3(1, mTiles, NMP), 256>>>(NTn, AVd, ga);
    }
    beta_kernel<<<1, 32>>>(1);
    final_kernel<<<NTGTn, 256>>>(stb, stb + SLABST, bp, lW1, lb1, tgt, out);
}

// round 3
// speedup vs baseline: 1.4941x; 1.3084x over previous
#include <cuda_runtime.h>
#include <math.h>

#define NTn     34000
#define NTYPES  3
#define NMP     2
#define ECNT    300000
#define HH      8
#define DD      64
#define HDIM    512
#define AVd     128
#define COUT    8
#define NTGTn   1000
#define NNODES  (NTYPES*NTn)
#define NSLAB   (NTYPES*NMP)

typedef unsigned long long u64;

// ---------------- scratch (device globals; no allocation) ----------------
__device__ float g_h0[(size_t)NNODES*DD];
__device__ float g_h1[(size_t)NNODES*DD];
__device__ float g_e [(size_t)NSLAB*ECNT*HH];   // per-edge logits, SORTED slot order
__device__ float g_st[(size_t)NSLAB*NTn*HDIM];
__device__ float g_u [(size_t)NSLAB*NTn*HH];    // t1[n0] + t2[n0]/3  (dst-local)
__device__ float g_t2[(size_t)NSLAB*NNODES*HH]; // h[n].a2 per head
__device__ int4  g_srt[(size_t)NSLAB*ECNT];     // sorted (n0,n1,n2,_) triples
__device__ int   g_counts[NSLAB*NTn];
__device__ int   g_ofs   [NSLAB*NTn];           // exclusive offsets; ofs[NTn]==ECNT implicit
__device__ int   g_cursor[NSLAB*NTn];
__device__ float g_s[NSLAB];
__device__ float g_beta[NSLAB];

// ---------------- f32x2 packed helpers ----------------
__device__ __forceinline__ u64 pack2(float x, float y) {
    u64 r; asm("mov.b64 %0, {%1, %2};" : "=l"(r) : "f"(x), "f"(y)); return r;
}
__device__ __forceinline__ void ffma2(u64& d, u64 a, u64 b) {
    asm("fma.rn.f32x2 %0, %1, %2, %0;" : "+l"(d) : "l"(a), "l"(b));
}
__device__ __forceinline__ float2 unpack2(u64 v) {
    float x, y; asm("mov.b64 {%0, %1}, %2;" : "=f"(x), "=f"(y) : "l"(v));
    return make_float2(x, y);
}

// ---------------- small utility kernels ----------------
__global__ void zero_i_kernel(int* p, int n) {
    int i = blockIdx.x*blockDim.x + threadIdx.x;
    if (i < n) p[i] = 0;
}
__global__ void zero_s_kernel() {
    if (threadIdx.x < NSLAB) g_s[threadIdx.x] = 0.f;
}
__global__ void beta_kernel(int ntypes) {
    int t = threadIdx.x;
    if (t < ntypes) {
        float s0 = g_s[t*2+0] * (1.f/(float)NTn);
        float s1 = g_s[t*2+1] * (1.f/(float)NTn);
        float m  = fmaxf(s0, s1);
        float e0 = expf(s0 - m), e1 = expf(s1 - m);
        float d  = e0 + e1;
        g_beta[t*2+0] = e0 / d;
        g_beta[t*2+1] = e1 / d;
    }
}

// ---------------- CSR construction ----------------
__global__ void hist_kernel(const int* __restrict__ mpidx, int* __restrict__ counts) {
    int slab = blockIdx.z;
    int e = blockIdx.x*blockDim.x + threadIdx.x;
    if (e < ECNT) {
        int dst = mpidx[(size_t)slab*ECNT*3 + e*3] - (slab/NMP)*NTn;
        atomicAdd(&counts[(size_t)slab*NTn + dst], 1);
    }
}

// 4-wide block scan: one block per slab, 4 counts/thread/tile
__global__ void scan_kernel(const int* __restrict__ countsAll,
                            int* __restrict__ ofsAll, int* __restrict__ cursorAll) {
    int slab = blockIdx.x;
    const int4* counts4 = (const int4*)(countsAll + (size_t)slab*NTn);
    int4* ofs4    = (int4*)(ofsAll    + (size_t)slab*NTn);
    int4* cursor4 = (int4*)(cursorAll + (size_t)slab*NTn);
    const int N4 = NTn/4;  // 8500
    __shared__ int warp_sums[32];
    __shared__ int s_carry;
    if (threadIdx.x == 0) s_carry = 0;
    __syncthreads();
    int lane = threadIdx.x & 31, wid = threadIdx.x >> 5;
    for (int base = 0; base < N4; base += 1024) {
        int i4 = base + threadIdx.x;
        int4 v = (i4 < N4) ? counts4[i4] : make_int4(0,0,0,0);
        int c1 = v.x, c2 = c1 + v.y, c3 = c2 + v.z, c4 = c3 + v.w;
        int tot = c4;
        int incl = tot;
        #pragma unroll
        for (int d = 1; d < 32; d <<= 1) {
            int t = __shfl_up_sync(0xffffffffu, incl, d);
            if (lane >= d) incl += t;
        }
        if (lane == 31) warp_sums[wid] = incl;
        __syncthreads();
        if (wid == 0) {
            int w = warp_sums[lane];
            #pragma unroll
            for (int d = 1; d < 32; d <<= 1) {
                int t = __shfl_up_sync(0xffffffffu, w, d);
                if (lane >= d) w += t;
            }
            warp_sums[lane] = w;
        }
        __syncthreads();
        int add = s_carry + (wid > 0 ? warp_sums[wid-1] : 0);
        int be  = add + incl - tot;
        if (i4 < N4) {
            int4 o = make_int4(be, be + c1, be + c2, be + c3);
            ofs4[i4] = o;
            cursor4[i4] = o;
        }
        __syncthreads();
        if (threadIdx.x == 1023) s_carry = add + incl;
        __syncthreads();
    }
}

__global__ void scatter_kernel(const int* __restrict__ mpidx, int* __restrict__ cursorAll) {
    int slab = blockIdx.z;
    int e = blockIdx.x*blockDim.x + threadIdx.x;
    if (e < ECNT) {
        const int* mp = mpidx + (size_t)slab*ECNT*3 + (size_t)e*3;
        int n0 = mp[0], n1 = mp[1], n2 = mp[2];
        int dst = n0 - (slab/NMP)*NTn;
        int pos = atomicAdd(&cursorAll[(size_t)slab*NTn + dst], 1);
        g_srt[(size_t)slab*ECNT + pos] = make_int4(n0, n1, n2, 0);
    }
}

// ---------------- per-node attention dot products (warp per node) ----------------
__global__ __launch_bounds__(256)
void dot_kernel(const float* __restrict__ h, const float* __restrict__ attn1,
                const float* __restrict__ attn2, int layerOff) {
    int slab = blockIdx.z;
    size_t aoff = (size_t)(layerOff + slab)*HH*DD;
    __shared__ float a1s[HH*DD];
    __shared__ float a2s[HH*DD];
    for (int i = threadIdx.x; i < HH*DD; i += blockDim.x) {
        a1s[i] = attn1[aoff + i];
        a2s[i] = attn2[aoff + i];
    }
    __syncthreads();
    int lane = threadIdx.x & 31;
    int wid  = threadIdx.x >> 5;
    int gn = blockIdx.x*8 + wid;
    if (gn >= NNODES) return;

    float hv0 = h[(size_t)gn*DD + lane];
    float hv1 = h[(size_t)gn*DD + 32 + lane];
    int ibase = (slab/NMP)*NTn;
    bool isdst = (gn >= ibase) && (gn < ibase + NTn);

    float r2[HH], r1[HH];
    #pragma unroll
    for (int hh = 0; hh < HH; hh++) {
        float v = hv0*a2s[hh*DD+lane] + hv1*a2s[hh*DD+32+lane];
        #pragma unroll
        for (int o = 16; o > 0; o >>= 1) v += __shfl_xor_sync(0xffffffffu, v, o);
        r2[hh] = v;
    }
    if (isdst) {
        #pragma unroll
        for (int hh = 0; hh < HH; hh++) {
            float v = hv0*a1s[hh*DD+lane] + hv1*a1s[hh*DD+32+lane];
            #pragma unroll
            for (int o = 16; o > 0; o >>= 1) v += __shfl_xor_sync(0xffffffffu, v, o);
            r1[hh] = v;
        }
    }
    float myt2 = 0.f, myu = 0.f;
    const float third = 1.f/3.f;
    #pragma unroll
    for (int hh = 0; hh < HH; hh++) {
        if (lane == hh) {
            myt2 = r2[hh];
            if (isdst) myu = r1[hh] + r2[hh]*third;
        }
    }
    if (lane < HH) {
        g_t2[((size_t)slab*NNODES + gn)*HH + lane] = myt2;
        if (isdst) g_u[((size_t)slab*NTn + (gn - ibase))*HH + lane] = myu;
    }
}

// ---------------- per-edge logits from precomputed dots (thread per sorted slot) ----------------
__global__ __launch_bounds__(256)
void edge_kernel() {
    int slab = blockIdx.z;
    size_t eb = (size_t)slab*ECNT;
    int e = blockIdx.x*256 + threadIdx.x;
    if (e >= ECNT) return;
    int4 tr = g_srt[eb + e];
    int ibase = (slab/NMP)*NTn;
    const float* up  = g_u  + ((size_t)slab*NTn + (tr.x - ibase))*HH;
    const float* t2b = g_t2 + (size_t)slab*NNODES*HH;
    float4 u0 = *(const float4*)(up);
    float4 u1 = *(const float4*)(up + 4);
    float4 p0 = *(const float4*)(t2b + (size_t)tr.y*HH);
    float4 p1 = *(const float4*)(t2b + (size_t)tr.y*HH + 4);
    float4 q0 = *(const float4*)(t2b + (size_t)tr.z*HH);
    float4 q1 = *(const float4*)(t2b + (size_t)tr.z*HH + 4);
    const float third = 1.f/3.f;
    float ev[HH];
    ev[0] = u0.x + (p0.x+q0.x)*third;  ev[1] = u0.y + (p0.y+q0.y)*third;
    ev[2] = u0.z + (p0.z+q0.z)*third;  ev[3] = u0.w + (p0.w+q0.w)*third;
    ev[4] = u1.x + (p1.x+q1.x)*third;  ev[5] = u1.y + (p1.y+q1.y)*third;
    ev[6] = u1.z + (p1.z+q1.z)*third;  ev[7] = u1.w + (p1.w+q1.w)*third;
    #pragma unroll
    for (int hh = 0; hh < HH; hh++)
        ev[hh] = (ev[hh] > 0.f) ? ev[hh] : 0.2f*ev[hh];
    float* dst = g_e + (eb + (size_t)e)*HH;
    *(float4*)(dst)     = make_float4(ev[0], ev[1], ev[2], ev[3]);
    *(float4*)(dst + 4) = make_float4(ev[4], ev[5], ev[6], ev[7]);
}

// ---------------- segment softmax + weighted sum (warp per node) ----------------
__global__ __launch_bounds__(256)
void node_kernel(const float* __restrict__ h) {
    int slab = blockIdx.z;
    const int*  ofs = g_ofs + (size_t)slab*NTn;
    const int4* srt = g_srt + (size_t)slab*ECNT;
    const float* eArr = g_e + (size_t)slab*ECNT*HH;
    float* st = g_st + (size_t)slab*NTn*HDIM;

    int lane = threadIdx.x & 31;
    int wid  = threadIdx.x >> 5;
    int n = blockIdx.x*8 + wid;
    if (n >= NTn) return;

    int s0 = ofs[n];
    int s1 = (n < NTn-1) ? ofs[n+1] : ECNT;
    if (s1 == s0) {  // empty segment -> st row = elu(0) = 0
        #pragma unroll
        for (int hh = 0; hh < HH; hh++) {
            st[(size_t)n*HDIM + hh*DD + lane]      = 0.f;
            st[(size_t)n*HDIM + hh*DD + 32 + lane] = 0.f;
        }
        return;
    }
    int ibase = (slab/NMP)*NTn;

    // pass 1: per-head max (sequential coalesced reads of sorted e)
    float mh[HH];
    #pragma unroll
    for (int hh = 0; hh < HH; hh++) mh[hh] = -3.402823466e38f;
    for (int j = s0 + lane; j < s1; j += 32) {
        float4 e0 = *(const float4*)(eArr + (size_t)j*HH);
        float4 e1 = *(const float4*)(eArr + (size_t)j*HH + 4);
        mh[0]=fmaxf(mh[0],e0.x); mh[1]=fmaxf(mh[1],e0.y);
        mh[2]=fmaxf(mh[2],e0.z); mh[3]=fmaxf(mh[3],e0.w);
        mh[4]=fmaxf(mh[4],e1.x); mh[5]=fmaxf(mh[5],e1.y);
        mh[6]=fmaxf(mh[6],e1.z); mh[7]=fmaxf(mh[7],e1.w);
    }
    #pragma unroll
    for (int hh = 0; hh < HH; hh++) {
        #pragma unroll
        for (int o = 16; o > 0; o >>= 1)
            mh[hh] = fmaxf(mh[hh], __shfl_xor_sync(0xffffffffu, mh[hh], o));
    }
    float myM = 0.f;
    #pragma unroll
    for (int hh = 0; hh < HH; hh++) if (lane == hh) myM = mh[hh];

    // pass 2: chunked (MLP) accumulation of den and ex-weighted mid-node features
    float den = 0.f;
    float acc[2*HH];
    #pragma unroll
    for (int k = 0; k < 2*HH; k++) acc[k] = 0.f;

    for (int j = s0; j < s1; j += 4) {
        int m = s1 - j; if (m > 4) m = 4;
        int nn1[4], nn2[4];
        #pragma unroll
        for (int c = 0; c < 4; c++) {
            int jj = j + ((c < m) ? c : 0);
            int4 tr = srt[jj];
            nn1[c] = tr.y; nn2[c] = tr.z;
        }
        float exv[4];
        #pragma unroll
        for (int c = 0; c < 4; c++) {
            float evl = 0.f;
            if (lane < HH && c < m)
                evl = expf(eArr[(size_t)(j+c)*HH + lane] - myM);
            exv[c] = evl;
            den += evl;
        }
        float f1a[4], f1b[4], f2a[4], f2b[4];
        #pragma unroll
        for (int c = 0; c < 4; c++) {
            f1a[c] = h[(size_t)nn1[c]*DD + lane];
            f1b[c] = h[(size_t)nn1[c]*DD + 32 + lane];
            f2a[c] = h[(size_t)nn2[c]*DD + lane];
            f2b[c] = h[(size_t)nn2[c]*DD + 32 + lane];
        }
        #pragma unroll
        for (int c = 0; c < 4; c++) {
            float sa = f1a[c] + f2a[c];
            float sb = f1b[c] + f2b[c];
            #pragma unroll
            for (int hh = 0; hh < HH; hh++) {
                float exh = __shfl_sync(0xffffffffu, exv[c], hh);
                acc[hh*2+0] += exh * sa;
                acc[hh*2+1] += exh * sb;
            }
        }
    }

    float hn0a = h[(size_t)(ibase+n)*DD + lane];
    float hn0b = h[(size_t)(ibase+n)*DD + 32 + lane];
    const float third = 1.f/3.f;
    #pragma unroll
    for (int hh = 0; hh < HH; hh++) {
        float dh = __shfl_sync(0xffffffffu, den, hh);
        float inv = 1.f / dh;   // den >= 1 (max element contributes 1)
        float v0 = (hn0a + acc[hh*2+0]*inv) * third;
        float v1 = (hn0b + acc[hh*2+1]*inv) * third;
        v0 = (v0 > 0.f) ? v0 : (expf(v0) - 1.f);
        v1 = (v1 > 0.f) ? v1 : (expf(v1) - 1.f);
        st[(size_t)n*HDIM + hh*DD + lane]      = v0;
        st[(size_t)n*HDIM + hh*DD + 32 + lane] = v1;
    }
}

// ---------------- tiled SGEMM (f32x2, sw-pipelined) with fused epilogues ----------------
// MODE 0: C = A0 @ B + bias
// MODE 1: atomicAdd(sOut, sum_rows( tanh(A0@B + bias) . q ))
// MODE 2: C = elu( (beta0*A0 + beta1*A1) @ B + bias )
struct GArgs {
    const float* A0; const float* A1;
    const float* B;  const float* bias;
    const float* q;  const float* beta2;
    float* C; float* sOut; int K;
};
struct GArgsN { GArgs z[NSLAB]; };

template<int BM, int BN, int BK, int TM, int TN, int MODE>
__global__ __launch_bounds__((BM/TM)*(BN/TN))
void gemm_kernel(int M, int N, GArgsN ga) {
    constexpr int THREADS = (BM/TM)*(BN/TN);
    constexpr int AL = (BM*BK)/(4*THREADS);
    constexpr int BL = (BK*BN)/(4*THREADS);
    const GArgs g = ga.z[blockIdx.z];
    __shared__ __align__(16) float As[BK][BM];
    __shared__ __align__(16) float Bs[BK][BN];
    const int tid = threadIdx.x;
    const int tx  = tid % (BN/TN);
    const int ty  = tid / (BN/TN);
    const int mBase = blockIdx.y * BM;
    const int nBase = blockIdx.x * BN;
    const int K = g.K;

    u64 acc2[TM/2][TN];
    #pragma unroll
    for (int u = 0; u < TM/2; u++)
        #pragma unroll
        for (int j = 0; j < TN; j++) acc2[u][j] = 0ull;

    float cb0 = 0.f, cb1 = 0.f;
    if (MODE == 2) { cb0 = g.beta2[0]; cb1 = g.beta2[1]; }

    float4 rA0[AL], rA1[AL], rB[BL];
    int aRow[AL], aKq[AL], bKk[BL], bNq[BL];
    #pragma unroll
    for (int l = 0; l < AL; l++) {
        int t = tid + l*THREADS;
        aRow[l] = t / (BK/4);
        aKq[l]  = t % (BK/4);
    }
    #pragma unroll
    for (int l = 0; l < BL; l++) {
        int t = tid + l*THREADS;
        bKk[l] = t / (BN/4);
        bNq[l] = t % (BN/4);
    }

    auto loadTile = [&](int k0) {
        #pragma unroll
        for (int l = 0; l < AL; l++) {
            int gr = mBase + aRow[l];
            float4 v = make_float4(0.f,0.f,0.f,0.f);
            float4 w = make_float4(0.f,0.f,0.f,0.f);
            if (gr < M) {
                v = *(const float4*)(g.A0 + (size_t)gr*K + k0 + aKq[l]*4);
                if (MODE == 2)
                    w = *(const float4*)(g.A1 + (size_t)gr*K + k0 + aKq[l]*4);
            }
            rA0[l] = v;
            if (MODE == 2) rA1[l] = w;
        }
        #pragma unroll
        for (int l = 0; l < BL; l++)
            rB[l] = *(const float4*)(g.B + (size_t)(k0+bKk[l])*N + nBase + bNq[l]*4);
    };

    loadTile(0);
    for (int k0 = 0; k0 < K; k0 += BK) {
        __syncthreads();
        #pragma unroll
        for (int l = 0; l < AL; l++) {
            float4 v = rA0[l];
            if (MODE == 2) {
                float4 w = rA1[l];
                v.x = cb0*v.x + cb1*w.x;  v.y = cb0*v.y + cb1*w.y;
                v.z = cb0*v.z + cb1*w.z;  v.w = cb0*v.w + cb1*w.w;
            }
            As[aKq[l]*4+0][aRow[l]] = v.x;
            As[aKq[l]*4+1][aRow[l]] = v.y;
            As[aKq[l]*4+2][aRow[l]] = v.z;
            As[aKq[l]*4+3][aRow[l]] = v.w;
        }
        #pragma unroll
        for (int l = 0; l < BL; l++)
            *(float4*)&Bs[bKk[l]][bNq[l]*4] = rB[l];
        __syncthreads();
        if (k0 + BK < K) loadTile(k0 + BK);
        #pragma unroll
        for (int kk = 0; kk < BK; kk++) {
            u64 a2[TM/2];
            #pragma unroll
            for (int u = 0; u < TM/2; u++)
                a2[u] = *(const u64*)&As[kk][ty*TM + 2*u];
            float bf[TN];
            #pragma unroll
            for (int jq = 0; jq < TN/4; jq++) {
                float4 bv = *(const float4*)&Bs[kk][tx*TN + jq*4];
                bf[jq*4+0] = bv.x; bf[jq*4+1] = bv.y;
                bf[jq*4+2] = bv.z; bf[jq*4+3] = bv.w;
            }
            #pragma unroll
            for (int j = 0; j < TN; j++) {
                u64 bb = pack2(bf[j], bf[j]);
                #pragma unroll
                for (int u = 0; u < TM/2; u++)
                    ffma2(acc2[u][j], a2[u], bb);
            }
        }
    }

    if (MODE == 1) {
        float local = 0.f;
        #pragma unroll
        for (int u = 0; u < TM/2; u++) {
            int gr0 = mBase + ty*TM + 2*u;
            int gr1 = gr0 + 1;
            #pragma unroll
            for (int j = 0; j < TN; j++) {
                int col = nBase + tx*TN + j;
                float2 v = unpack2(acc2[u][j]);
                float bq = g.q[col];
                float bb = g.bias[col];
                if (gr0 < M) local += tanhf(v.x + bb) * bq;
                if (gr1 < M) local += tanhf(v.y + bb) * bq;
            }
        }
        __shared__ float red[THREADS];
        red[tid] = local;
        __syncthreads();
        #pragma unroll
        for (int s2 = THREADS/2; s2 > 0; s2 >>= 1) {
            if (tid < s2) red[tid] += red[tid + s2];
            __syncthreads();
        }
        if (tid == 0) atomicAdd(g.sOut, red[0]);
    } else {
        #pragma unroll
        for (int u = 0; u < TM/2; u++) {
            int gr0 = mBase + ty*TM + 2*u;
            int gr1 = gr0 + 1;
            #pragma unroll
            for (int j = 0; j < TN; j++) {
                int col = nBase + tx*TN + j;
                float2 v = unpack2(acc2[u][j]);
                float bb = g.bias[col];
                float x = v.x + bb, y = v.y + bb;
                if (MODE == 2) {
                    x = (x > 0.f) ? x : (expf(x) - 1.f);
                    y = (y > 0.f) ? y : (expf(y) - 1.f);
                }
                if (gr0 < M) g.C[(size_t)gr0*N + col] = x;
                if (gr1 < M) g.C[(size_t)gr1*N + col] = y;
            }
        }
    }
}

// ---------------- final logits at target rows ----------------
__global__ __launch_bounds__(256)
void final_kernel(const float* __restrict__ st0, const float* __restrict__ st1,
                  const float* __restrict__ betaPtr,
                  const float* __restrict__ lW1, const float* __restrict__ lb1,
                  const int* __restrict__ tgt, float* __restrict__ out) {
    int t    = blockIdx.x;
    int col  = threadIdx.x >> 5;
    int lane = threadIdx.x & 31;
    int n = tgt[t];
    float b0 = betaPtr[0], b1 = betaPtr[1];
    float acc = 0.f;
    for (int k = lane; k < HDIM; k += 32) {
        float a = b0*st0[(size_t)n*HDIM + k] + b1*st1[(size_t)n*HDIM + k];
        acc += a * lW1[(size_t)k*COUT + col];
    }
    #pragma unroll
    for (int o = 16; o > 0; o >>= 1) acc += __shfl_xor_sync(0xffffffffu, acc, o);
    if (lane == 0) out[(size_t)t*COUT + col] = acc + lb1[col];
}

// ---------------- host orchestration ----------------
extern "C" void kernel_launch(void* const* d_in, const int* in_sizes, int n_in,
                              void* d_out, int out_size) {
    const float* X0   = (const float*)d_in[0];
    const float* X1   = (const float*)d_in[1];
    const float* X2   = (const float*)d_in[2];
    const float* fcW[3] = {(const float*)d_in[3], (const float*)d_in[5], (const float*)d_in[7]};
    const float* fcb[3] = {(const float*)d_in[4], (const float*)d_in[6], (const float*)d_in[8]};
    const float* attn1 = (const float*)d_in[9];
    const float* attn2 = (const float*)d_in[10];
    const float* mpW   = (const float*)d_in[11];
    const float* mpb   = (const float*)d_in[12];
    const float* mpq   = (const float*)d_in[13];
    const float* lW0   = (const float*)d_in[14];
    const float* lb0   = (const float*)d_in[15];
    const float* lW1   = (const float*)d_in[16];
    const float* lb1   = (const float*)d_in[17];
    const int*   mpidx = (const int*)d_in[18];
    const int*   tgt   = (const int*)d_in[19];
    float* out = (float*)d_out;

    float *h0, *h1, *stb, *sp, *bp;
    int *cnt, *ofs, *cur;
    cudaGetSymbolAddress((void**)&h0,  g_h0);
    cudaGetSymbolAddress((void**)&h1,  g_h1);
    cudaGetSymbolAddress((void**)&stb, g_st);
    cudaGetSymbolAddress((void**)&sp,  g_s);
    cudaGetSymbolAddress((void**)&bp,  g_beta);
    cudaGetSymbolAddress((void**)&cnt, g_counts);
    cudaGetSymbolAddress((void**)&ofs, g_ofs);
    cudaGetSymbolAddress((void**)&cur, g_cursor);

    const size_t SLABST = (size_t)NTn*HDIM;
    const int mTiles = (NTn + 127) / 128;

    zero_i_kernel<<<(NSLAB*NTn + 255)/256, 256>>>(cnt, NSLAB*NTn);

    // per-type feature FC -> h0 (batched z=3)
    {
        GArgsN ga = {};
        const float* Xs[3] = {X0, X1, X2};
        const int    Ks[3] = {512, 256, 128};
        for (int i = 0; i < NTYPES; i++) {
            ga.z[i].A0 = Xs[i]; ga.z[i].B = fcW[i]; ga.z[i].bias = fcb[i];
            ga.z[i].C  = h0 + (size_t)i*NTn*DD; ga.z[i].K = Ks[i];
        }
        gemm_kernel<128,64,16,8,4,0><<<dim3(1, mTiles, NTYPES), 256>>>(NTn, DD, ga);
    }

    // CSR build (sorted triples)
    hist_kernel   <<<dim3((ECNT+255)/256, 1, NSLAB), 256>>>(mpidx, cnt);
    scan_kernel   <<<NSLAB, 1024>>>(cnt, ofs, cur);
    scatter_kernel<<<dim3((ECNT+255)/256, 1, NSLAB), 256>>>(mpidx, cur);

    for (int l = 0; l < 2; l++) {
        const float* hin = (l == 0) ? h0 : h1;
        int nslab  = (l == 0) ? NSLAB : NMP;     // layer 1: only type 0
        int ntypes = (l == 0) ? NTYPES : 1;

        dot_kernel <<<dim3((NNODES+7)/8, 1, nslab), 256>>>(hin, attn1, attn2, l*NSLAB);
        edge_kernel<<<dim3((ECNT+255)/256, 1, nslab), 256>>>();
        node_kernel<<<dim3((NTn+7)/8, 1, nslab), 256>>>(hin);

        zero_s_kernel<<<1, 32>>>();
        {
            GArgsN ga = {};
            for (int zz = 0; zz < nslab; zz++) {
                int type = (l == 0) ? (zz / NMP) : 0;
                int mi = l*NTYPES + type;
                ga.z[zz].A0   = stb + (size_t)zz*SLABST;
                ga.z[zz].B    = mpW + (size_t)mi*HDIM*AVd;
                ga.z[zz].bias = mpb + (size_t)mi*AVd;
                ga.z[zz].q    = mpq + (size_t)mi*AVd;
                ga.z[zz].sOut = sp + zz;
                ga.z[zz].K    = HDIM;
            }
            gemm_kernel<128,128,16,8,8,1><<<dim3(1, mTiles, nslab), 256>>>(NTn, AVd, ga);
        }
        beta_kernel<<<1, 32>>>(ntypes);

        if (l == 0) {
            GArgsN ga = {};
            for (int t = 0; t < NTYPES; t++) {
                ga.z[t].A0 = stb + (size_t)(t*2+0)*SLABST;
                ga.z[t].A1 = stb + (size_t)(t*2+1)*SLABST;
                ga.z[t].beta2 = bp + t*2;
                ga.z[t].B = lW0; ga.z[t].bias = lb0;
                ga.z[t].C = h1 + (size_t)t*NTn*DD;
                ga.z[t].K = HDIM;
            }
            gemm_kernel<128,64,16,8,4,2><<<dim3(1, mTiles, NTYPES), 256>>>(NTn, DD, ga);
        } else {
            final_kernel<<<NTGTn, 256>>>(stb, stb + SLABST, bp, lW1, lb1, tgt, out);
        }
    }
}

// round 5
// speedup vs baseline: 2.2162x; 1.4833x over previous
#include <cuda_runtime.h>
#include <cuda_bf16.h>
#include <math.h>
#include <stdint.h>

#define NTn     34000
#define NTYPES  3
#define NMP     2
#define ECNT    300000
#define HH      8
#define DD      64
#define HDIM    512
#define AVd     128
#define COUT    8
#define NTGTn   1000
#define NNODES  (NTYPES*NTn)
#define NSLAB   (NTYPES*NMP)

typedef unsigned long long u64;

// ---------------- scratch (device globals; no allocation) ----------------
__device__ float g_h0[(size_t)NNODES*DD];
__device__ float g_h1[(size_t)NNODES*DD];
__device__ float g_e [(size_t)NSLAB*ECNT*HH];
__device__ float g_st[(size_t)NSLAB*NTn*HDIM];
__device__ float g_u [(size_t)NSLAB*NTn*HH];
__device__ float g_t2[(size_t)NSLAB*NNODES*HH];
__device__ int4  g_srt[(size_t)NSLAB*ECNT];
__device__ int   g_counts[NSLAB*NTn];
__device__ int   g_ofs   [NSLAB*NTn];
__device__ int   g_cursor[NSLAB*NTn];
__device__ float g_s[NSLAB];
__device__ float g_beta[NSLAB];
__device__ __nv_bfloat16 g_bt[(size_t)(NTYPES+1)*AVd*HDIM];  // mpW^T bf16, 4 matrices

// ---------------- f32x2 packed helpers ----------------
__device__ __forceinline__ u64 pack2(float x, float y) {
    u64 r; asm("mov.b64 %0, {%1, %2};" : "=l"(r) : "f"(x), "f"(y)); return r;
}
__device__ __forceinline__ void ffma2(u64& d, u64 a, u64 b) {
    asm("fma.rn.f32x2 %0, %1, %2, %0;" : "+l"(d) : "l"(a), "l"(b));
}
__device__ __forceinline__ float2 unpack2(u64 v) {
    float x, y; asm("mov.b64 {%0, %1}, %2;" : "=f"(x), "=f"(y) : "l"(v));
    return make_float2(x, y);
}
__device__ __forceinline__ float tanh_apx(float x) {
    float y; asm("tanh.approx.f32 %0, %1;" : "=f"(y) : "f"(x)); return y;
}
__device__ __forceinline__ uint32_t smem_u32(const void* p) {
    uint32_t a;
    asm("{ .reg .u64 t; cvta.to.shared.u64 t, %1; cvt.u32.u64 %0, t; }"
        : "=r"(a) : "l"(p));
    return a;
}

// ---------------- small utility kernels ----------------
__global__ void zero_i_kernel(int* p, int n) {
    int i = blockIdx.x*blockDim.x + threadIdx.x;
    if (i < n) p[i] = 0;
}
__global__ void zero_s_kernel() {
    if (threadIdx.x < NSLAB) g_s[threadIdx.x] = 0.f;
}
__global__ void beta_kernel(int ntypes) {
    int t = threadIdx.x;
    if (t < ntypes) {
        float s0 = g_s[t*2+0] * (1.f/(float)NTn);
        float s1 = g_s[t*2+1] * (1.f/(float)NTn);
        float m  = fmaxf(s0, s1);
        float e0 = expf(s0 - m), e1 = expf(s1 - m);
        float d  = e0 + e1;
        g_beta[t*2+0] = e0 / d;
        g_beta[t*2+1] = e1 / d;
    }
}
// transpose mpW [mi][HDIM][AVd] -> bf16 [mi][AVd][HDIM]  (mi: 3 layer0 types + 1 layer1)
__global__ void transW_kernel(const float* __restrict__ mpW) {
    int mi = blockIdx.z;
    int t = blockIdx.x*256 + threadIdx.x;
    if (t < AVd*HDIM) {
        int n = t >> 9;
        int k = t & 511;
        float v = mpW[(size_t)mi*HDIM*AVd + (size_t)k*AVd + n];
        g_bt[(size_t)mi*AVd*HDIM + (size_t)n*HDIM + k] = __float2bfloat16(v);
    }
}

// ---------------- CSR construction ----------------
__global__ void hist_kernel(const int* __restrict__ mpidx, int* __restrict__ counts) {
    int slab = blockIdx.z;
    int e = blockIdx.x*blockDim.x + threadIdx.x;
    if (e < ECNT) {
        int dst = mpidx[(size_t)slab*ECNT*3 + e*3] - (slab/NMP)*NTn;
        atomicAdd(&counts[(size_t)slab*NTn + dst], 1);
    }
}

__global__ void scan_kernel(const int* __restrict__ countsAll,
                            int* __restrict__ ofsAll, int* __restrict__ cursorAll) {
    int slab = blockIdx.x;
    const int4* counts4 = (const int4*)(countsAll + (size_t)slab*NTn);
    int4* ofs4    = (int4*)(ofsAll    + (size_t)slab*NTn);
    int4* cursor4 = (int4*)(cursorAll + (size_t)slab*NTn);
    const int N4 = NTn/4;
    __shared__ int warp_sums[32];
    __shared__ int s_carry;
    if (threadIdx.x == 0) s_carry = 0;
    __syncthreads();
    int lane = threadIdx.x & 31, wid = threadIdx.x >> 5;
    for (int base = 0; base < N4; base += 1024) {
        int i4 = base + threadIdx.x;
        int4 v = (i4 < N4) ? counts4[i4] : make_int4(0,0,0,0);
        int c1 = v.x, c2 = c1 + v.y, c3 = c2 + v.z, c4 = c3 + v.w;
        int tot = c4;
        int incl = tot;
        #pragma unroll
        for (int d = 1; d < 32; d <<= 1) {
            int t = __shfl_up_sync(0xffffffffu, incl, d);
            if (lane >= d) incl += t;
        }
        if (lane == 31) warp_sums[wid] = incl;
        __syncthreads();
        if (wid == 0) {
            int w = warp_sums[lane];
            #pragma unroll
            for (int d = 1; d < 32; d <<= 1) {
                int t = __shfl_up_sync(0xffffffffu, w, d);
                if (lane >= d) w += t;
            }
            warp_sums[lane] = w;
        }
        __syncthreads();
        int add = s_carry + (wid > 0 ? warp_sums[wid-1] : 0);
        int be  = add + incl - tot;
        if (i4 < N4) {
            int4 o = make_int4(be, be + c1, be + c2, be + c3);
            ofs4[i4] = o;
            cursor4[i4] = o;
        }
        __syncthreads();
        if (threadIdx.x == 1023) s_carry = add + incl;
        __syncthreads();
    }
}

__global__ void scatter_kernel(const int* __restrict__ mpidx, int* __restrict__ cursorAll) {
    int slab = blockIdx.z;
    int e = blockIdx.x*blockDim.x + threadIdx.x;
    if (e < ECNT) {
        const int* mp = mpidx + (size_t)slab*ECNT*3 + (size_t)e*3;
        int n0 = mp[0], n1 = mp[1], n2 = mp[2];
        int dst = n0 - (slab/NMP)*NTn;
        int pos = atomicAdd(&cursorAll[(size_t)slab*NTn + dst], 1);
        g_srt[(size_t)slab*ECNT + pos] = make_int4(n0, n1, n2, 0);
    }
}

// ---------------- per-node attention dot products (warp per node) ----------------
__global__ __launch_bounds__(256)
void dot_kernel(const float* __restrict__ h, const float* __restrict__ attn1,
                const float* __restrict__ attn2, int layerOff) {
    int slab = blockIdx.z;
    size_t aoff = (size_t)(layerOff + slab)*HH*DD;
    __shared__ float a1s[HH*DD];
    __shared__ float a2s[HH*DD];
    for (int i = threadIdx.x; i < HH*DD; i += blockDim.x) {
        a1s[i] = attn1[aoff + i];
        a2s[i] = attn2[aoff + i];
    }
    __syncthreads();
    int lane = threadIdx.x & 31;
    int wid  = threadIdx.x >> 5;
    int gn = blockIdx.x*8 + wid;
    if (gn >= NNODES) return;

    float hv0 = h[(size_t)gn*DD + lane];
    float hv1 = h[(size_t)gn*DD + 32 + lane];
    int ibase = (slab/NMP)*NTn;
    bool isdst = (gn >= ibase) && (gn < ibase + NTn);

    float r2[HH], r1[HH];
    #pragma unroll
    for (int hh = 0; hh < HH; hh++) {
        float v = hv0*a2s[hh*DD+lane] + hv1*a2s[hh*DD+32+lane];
        #pragma unroll
        for (int o = 16; o > 0; o >>= 1) v += __shfl_xor_sync(0xffffffffu, v, o);
        r2[hh] = v;
    }
    if (isdst) {
        #pragma unroll
        for (int hh = 0; hh < HH; hh++) {
            float v = hv0*a1s[hh*DD+lane] + hv1*a1s[hh*DD+32+lane];
            #pragma unroll
            for (int o = 16; o > 0; o >>= 1) v += __shfl_xor_sync(0xffffffffu, v, o);
            r1[hh] = v;
        }
    }
    float myt2 = 0.f, myu = 0.f;
    const float third = 1.f/3.f;
    #pragma unroll
    for (int hh = 0; hh < HH; hh++) {
        if (lane == hh) {
            myt2 = r2[hh];
            if (isdst) myu = r1[hh] + r2[hh]*third;
        }
    }
    if (lane < HH) {
        g_t2[((size_t)slab*NNODES + gn)*HH + lane] = myt2;
        if (isdst) g_u[((size_t)slab*NTn + (gn - ibase))*HH + lane] = myu;
    }
}

// ---------------- per-edge logits from precomputed dots ----------------
__global__ __launch_bounds__(256)
void edge_kernel() {
    int slab = blockIdx.z;
    size_t eb = (size_t)slab*ECNT;
    int e = blockIdx.x*256 + threadIdx.x;
    if (e >= ECNT) return;
    int4 tr = g_srt[eb + e];
    int ibase = (slab/NMP)*NTn;
    const float* up  = g_u  + ((size_t)slab*NTn + (tr.x - ibase))*HH;
    const float* t2b = g_t2 + (size_t)slab*NNODES*HH;
    float4 u0 = *(const float4*)(up);
    float4 u1 = *(const float4*)(up + 4);
    float4 p0 = *(const float4*)(t2b + (size_t)tr.y*HH);
    float4 p1 = *(const float4*)(t2b + (size_t)tr.y*HH + 4);
    float4 q0 = *(const float4*)(t2b + (size_t)tr.z*HH);
    float4 q1 = *(const float4*)(t2b + (size_t)tr.z*HH + 4);
    const float third = 1.f/3.f;
    float ev[HH];
    ev[0] = u0.x + (p0.x+q0.x)*third;  ev[1] = u0.y + (p0.y+q0.y)*third;
    ev[2] = u0.z + (p0.z+q0.z)*third;  ev[3] = u0.w + (p0.w+q0.w)*third;
    ev[4] = u1.x + (p1.x+q1.x)*third;  ev[5] = u1.y + (p1.y+q1.y)*third;
    ev[6] = u1.z + (p1.z+q1.z)*third;  ev[7] = u1.w + (p1.w+q1.w)*third;
    #pragma unroll
    for (int hh = 0; hh < HH; hh++)
        ev[hh] = (ev[hh] > 0.f) ? ev[hh] : 0.2f*ev[hh];
    float* dst = g_e + (eb + (size_t)e)*HH;
    *(float4*)(dst)     = make_float4(ev[0], ev[1], ev[2], ev[3]);
    *(float4*)(dst + 4) = make_float4(ev[4], ev[5], ev[6], ev[7]);
}

// ---------------- segment softmax + weighted sum (warp per node) ----------------
__global__ __launch_bounds__(256)
void node_kernel(const float* __restrict__ h) {
    int slab = blockIdx.z;
    const int*  ofs = g_ofs + (size_t)slab*NTn;
    const int4* srt = g_srt + (size_t)slab*ECNT;
    const float* eArr = g_e + (size_t)slab*ECNT*HH;
    float* st = g_st + (size_t)slab*NTn*HDIM;

    int lane = threadIdx.x & 31;
    int wid  = threadIdx.x >> 5;
    int n = blockIdx.x*8 + wid;
    if (n >= NTn) return;

    int s0 = ofs[n];
    int s1 = (n < NTn-1) ? ofs[n+1] : ECNT;
    if (s1 == s0) {
        #pragma unroll
        for (int hh = 0; hh < HH; hh++) {
            st[(size_t)n*HDIM + hh*DD + lane]      = 0.f;
            st[(size_t)n*HDIM + hh*DD + 32 + lane] = 0.f;
        }
        return;
    }
    int ibase = (slab/NMP)*NTn;

    float mh[HH];
    #pragma unroll
    for (int hh = 0; hh < HH; hh++) mh[hh] = -3.402823466e38f;
    for (int j = s0 + lane; j < s1; j += 32) {
        float4 e0 = *(const float4*)(eArr + (size_t)j*HH);
        float4 e1 = *(const float4*)(eArr + (size_t)j*HH + 4);
        mh[0]=fmaxf(mh[0],e0.x); mh[1]=fmaxf(mh[1],e0.y);
        mh[2]=fmaxf(mh[2],e0.z); mh[3]=fmaxf(mh[3],e0.w);
        mh[4]=fmaxf(mh[4],e1.x); mh[5]=fmaxf(mh[5],e1.y);
        mh[6]=fmaxf(mh[6],e1.z); mh[7]=fmaxf(mh[7],e1.w);
    }
    #pragma unroll
    for (int hh = 0; hh < HH; hh++) {
        #pragma unroll
        for (int o = 16; o > 0; o >>= 1)
            mh[hh] = fmaxf(mh[hh], __shfl_xor_sync(0xffffffffu, mh[hh], o));
    }
    float myM = 0.f;
    #pragma unroll
    for (int hh = 0; hh < HH; hh++) if (lane == hh) myM = mh[hh];

    float den = 0.f;
    float acc[2*HH];
    #pragma unroll
    for (int k = 0; k < 2*HH; k++) acc[k] = 0.f;

    for (int j = s0; j < s1; j += 4) {
        int m = s1 - j; if (m > 4) m = 4;
        int nn1[4], nn2[4];
        #pragma unroll
        for (int c = 0; c < 4; c++) {
            int jj = j + ((c < m) ? c : 0);
            int4 tr = srt[jj];
            nn1[c] = tr.y; nn2[c] = tr.z;
        }
        float exv[4];
        #pragma unroll
        for (int c = 0; c < 4; c++) {
            float evl = 0.f;
            if (lane < HH && c < m)
                evl = __expf(eArr[(size_t)(j+c)*HH + lane] - myM);
            exv[c] = evl;
            den += evl;
        }
        float f1a[4], f1b[4], f2a[4], f2b[4];
        #pragma unroll
        for (int c = 0; c < 4; c++) {
            f1a[c] = h[(size_t)nn1[c]*DD + lane];
            f1b[c] = h[(size_t)nn1[c]*DD + 32 + lane];
            f2a[c] = h[(size_t)nn2[c]*DD + lane];
            f2b[c] = h[(size_t)nn2[c]*DD + 32 + lane];
        }
        #pragma unroll
        for (int c = 0; c < 4; c++) {
            float sa = f1a[c] + f2a[c];
            float sb = f1b[c] + f2b[c];
            #pragma unroll
            for (int hh = 0; hh < HH; hh++) {
                float exh = __shfl_sync(0xffffffffu, exv[c], hh);
                acc[hh*2+0] += exh * sa;
                acc[hh*2+1] += exh * sb;
            }
        }
    }

    float hn0a = h[(size_t)(ibase+n)*DD + lane];
    float hn0b = h[(size_t)(ibase+n)*DD + 32 + lane];
    const float third = 1.f/3.f;
    #pragma unroll
    for (int hh = 0; hh < HH; hh++) {
        float dh = __shfl_sync(0xffffffffu, den, hh);
        float inv = 1.f / dh;
        float v0 = (hn0a + acc[hh*2+0]*inv) * third;
        float v1 = (hn0b + acc[hh*2+1]*inv) * third;
        v0 = (v0 > 0.f) ? v0 : (__expf(v0) - 1.f);
        v1 = (v1 > 0.f) ? v1 : (__expf(v1) - 1.f);
        st[(size_t)n*HDIM + hh*DD + lane]      = v0;
        st[(size_t)n*HDIM + hh*DD + 32 + lane] = v1;
    }
}

// ---------------- HMMA bf16 mode-1 GEMM: s += sum_rows(tanh(A@B^T + bias).q) ----
// Block 128x128x512 via mma.sync m16n8k16; 8 warps (2x4), warp tile 64x32.
struct T1Args { const float* A; const __nv_bfloat16* Bt;
                const float* bias; const float* q; float* sOut; };
struct T1ArgsN { T1Args z[NSLAB]; };

__global__ __launch_bounds__(256)
void mp_attn_kernel(int M, T1ArgsN ga) {
    constexpr int AP = 72;   // SMEM pitch (bf16): 144B rows, 16B-aligned, conflict-free
    __shared__ __align__(16) __nv_bfloat16 As[128*AP];
    __shared__ __align__(16) __nv_bfloat16 Bs[128*AP];
    __shared__ float sb_bias[128], sb_q[128];
    __shared__ float red[256];
    const T1Args g = ga.z[blockIdx.z];
    const int tid  = threadIdx.x;
    const int wid  = tid >> 5;
    const int lane = tid & 31;
    const int mBase = blockIdx.x * 128;
    const int wm = (wid >> 2) * 64;   // warp row base within tile
    const int wn = (wid & 3) * 32;    // warp col base within tile

    if (tid < 128) { sb_bias[tid] = g.bias[tid]; sb_q[tid] = g.q[tid]; }

    float d[4][4][4];
    #pragma unroll
    for (int mt = 0; mt < 4; mt++)
        #pragma unroll
        for (int nt = 0; nt < 4; nt++)
            #pragma unroll
            for (int f = 0; f < 4; f++) d[mt][nt][f] = 0.f;

    // global->reg load maps
    float4 ra[8]; uint4 rb[4];
    int aRow[8], aCol[8], bRow[4], bCol[4];
    #pragma unroll
    for (int i = 0; i < 8; i++) {
        int t = tid + i*256;
        aRow[i] = t >> 4;          // 0..127
        aCol[i] = (t & 15) * 4;    // 0..60
    }
    #pragma unroll
    for (int i = 0; i < 4; i++) {
        int t = tid + i*256;
        bRow[i] = t >> 3;          // 0..127
        bCol[i] = (t & 7) * 8;     // 0..56
    }

    auto loadRegs = [&](int c) {
        #pragma unroll
        for (int i = 0; i < 8; i++) {
            int gr = mBase + aRow[i];
            ra[i] = (gr < M)
                ? *(const float4*)(g.A + (size_t)gr*HDIM + c*64 + aCol[i])
                : make_float4(0.f, 0.f, 0.f, 0.f);
        }
        #pragma unroll
        for (int i = 0; i < 4; i++)
            rb[i] = *(const uint4*)(g.Bt + (size_t)bRow[i]*HDIM + c*64 + bCol[i]);
    };
    auto storeSmem = [&]() {
        #pragma unroll
        for (int i = 0; i < 8; i++) {
            __nv_bfloat162 p0 = __floats2bfloat162_rn(ra[i].x, ra[i].y);
            __nv_bfloat162 p1 = __floats2bfloat162_rn(ra[i].z, ra[i].w);
            uint2 u;
            u.x = *(uint32_t*)&p0;
            u.y = *(uint32_t*)&p1;
            *(uint2*)&As[aRow[i]*AP + aCol[i]] = u;
        }
        #pragma unroll
        for (int i = 0; i < 4; i++)
            *(uint4*)&Bs[bRow[i]*AP + bCol[i]] = rb[i];
    };

    uint32_t aSb = smem_u32(As);
    uint32_t bSb = smem_u32(Bs);

    loadRegs(0);
    #pragma unroll 1
    for (int c = 0; c < 8; c++) {
        storeSmem();
        __syncthreads();
        if (c < 7) loadRegs(c + 1);
        #pragma unroll
        for (int ks = 0; ks < 4; ks++) {
            uint32_t af[4][4];
            #pragma unroll
            for (int mt = 0; mt < 4; mt++) {
                uint32_t addr = aSb +
                    (((wm + mt*16 + (lane & 15))*AP + ks*16 + (lane >> 4)*8) << 1);
                asm volatile("ldmatrix.sync.aligned.m8n8.x4.shared.b16 {%0,%1,%2,%3}, [%4];"
                    : "=r"(af[mt][0]), "=r"(af[mt][1]), "=r"(af[mt][2]), "=r"(af[mt][3])
                    : "r"(addr));
            }
            uint32_t bf[4][2];
            #pragma unroll
            for (int nt = 0; nt < 4; nt++) {
                uint32_t addr = bSb +
                    (((wn + nt*8 + (lane & 7))*AP + ks*16 + ((lane >> 3) & 1)*8) << 1);
                asm volatile("ldmatrix.sync.aligned.m8n8.x2.shared.b16 {%0,%1}, [%2];"
                    : "=r"(bf[nt][0]), "=r"(bf[nt][1])
                    : "r"(addr));
            }
            #pragma unroll
            for (int mt = 0; mt < 4; mt++)
                #pragma unroll
                for (int nt = 0; nt < 4; nt++)
                    asm volatile(
                        "mma.sync.aligned.m16n8k16.row.col.f32.bf16.bf16.f32 "
                        "{%0,%1,%2,%3}, {%4,%5,%6,%7}, {%8,%9}, {%0,%1,%2,%3};"
                        : "+f"(d[mt][nt][0]), "+f"(d[mt][nt][1]),
                          "+f"(d[mt][nt][2]), "+f"(d[mt][nt][3])
                        : "r"(af[mt][0]), "r"(af[mt][1]), "r"(af[mt][2]), "r"(af[mt][3]),
                          "r"(bf[nt][0]), "r"(bf[nt][1]));
        }
        __syncthreads();
    }

    // epilogue: tanh(d + bias).q summed over valid rows
    int g8  = lane >> 2;
    int tig = lane & 3;
    float local = 0.f;
    #pragma unroll
    for (int mt = 0; mt < 4; mt++) {
        int r0 = mBase + wm + mt*16 + g8;
        int r1 = r0 + 8;
        #pragma unroll
        for (int nt = 0; nt < 4; nt++) {
            int c0 = wn + nt*8 + 2*tig;
            float b0v = sb_bias[c0],   q0v = sb_q[c0];
            float b1v = sb_bias[c0+1], q1v = sb_q[c0+1];
            if (r0 < M)
                local += tanh_apx(d[mt][nt][0] + b0v)*q0v
                       + tanh_apx(d[mt][nt][1] + b1v)*q1v;
            if (r1 < M)
                local += tanh_apx(d[mt][nt][2] + b0v)*q0v
                       + tanh_apx(d[mt][nt][3] + b1v)*q1v;
        }
    }
    red[tid] = local;
    __syncthreads();
    if (tid < 128) red[tid] += red[tid + 128];
    __syncthreads();
    if (tid < 64) red[tid] += red[tid + 64];
    __syncthreads();
    if (tid < 32) {
        float v = red[tid] + red[tid + 32];
        #pragma unroll
        for (int o = 16; o > 0; o >>= 1) v += __shfl_xor_sync(0xffffffffu, v, o);
        if (tid == 0) atomicAdd(g.sOut, v);
    }
}

// ---------------- tiled SGEMM (f32x2, sw-pipelined) with fused epilogues ----------------
// MODE 0: C = A0 @ B + bias      MODE 2: C = elu( (b0*A0 + b1*A1) @ B + bias )
struct GArgs {
    const float* A0; const float* A1;
    const float* B;  const float* bias;
    const float* beta2;
    float* C; int K;
};
struct GArgsN { GArgs z[NSLAB]; };

template<int BM, int BN, int BK, int TM, int TN, int MODE>
__global__ __launch_bounds__((BM/TM)*(BN/TN))
void gemm_kernel(int M, int N, GArgsN ga) {
    constexpr int THREADS = (BM/TM)*(BN/TN);
    constexpr int AL = (BM*BK)/(4*THREADS);
    constexpr int BL = (BK*BN)/(4*THREADS);
    const GArgs g = ga.z[blockIdx.z];
    __shared__ __align__(16) float As[BK][BM];
    __shared__ __align__(16) float Bs[BK][BN];
    const int tid = threadIdx.x;
    const int tx  = tid % (BN/TN);
    const int ty  = tid / (BN/TN);
    const int mBase = blockIdx.y * BM;
    const int nBase = blockIdx.x * BN;
    const int K = g.K;

    u64 acc2[TM/2][TN];
    #pragma unroll
    for (int u = 0; u < TM/2; u++)
        #pragma unroll
        for (int j = 0; j < TN; j++) acc2[u][j] = 0ull;

    float cb0 = 0.f, cb1 = 0.f;
    if (MODE == 2) { cb0 = g.beta2[0]; cb1 = g.beta2[1]; }

    float4 rA0[AL], rA1[AL], rB[BL];
    int aRow[AL], aKq[AL], bKk[BL], bNq[BL];
    #pragma unroll
    for (int l = 0; l < AL; l++) {
        int t = tid + l*THREADS;
        aRow[l] = t / (BK/4);
        aKq[l]  = t % (BK/4);
    }
    #pragma unroll
    for (int l = 0; l < BL; l++) {
        int t = tid + l*THREADS;
        bKk[l] = t / (BN/4);
        bNq[l] = t % (BN/4);
    }

    auto loadTile = [&](int k0) {
        #pragma unroll
        for (int l = 0; l < AL; l++) {
            int gr = mBase + aRow[l];
            float4 v = make_float4(0.f,0.f,0.f,0.f);
            float4 w = make_float4(0.f,0.f,0.f,0.f);
            if (gr < M) {
                v = *(const float4*)(g.A0 + (size_t)gr*K + k0 + aKq[l]*4);
                if (MODE == 2)
                    w = *(const float4*)(g.A1 + (size_t)gr*K + k0 + aKq[l]*4);
            }
            rA0[l] = v;
            if (MODE == 2) rA1[l] = w;
        }
        #pragma unroll
        for (int l = 0; l < BL; l++)
            rB[l] = *(const float4*)(g.B + (size_t)(k0+bKk[l])*N + nBase + bNq[l]*4);
    };

    loadTile(0);
    for (int k0 = 0; k0 < K; k0 += BK) {
        __syncthreads();
        #pragma unroll
        for (int l = 0; l < AL; l++) {
            float4 v = rA0[l];
            if (MODE == 2) {
                float4 w = rA1[l];
                v.x = cb0*v.x + cb1*w.x;  v.y = cb0*v.y + cb1*w.y;
                v.z = cb0*v.z + cb1*w.z;  v.w = cb0*v.w + cb1*w.w;
            }
            As[aKq[l]*4+0][aRow[l]] = v.x;
            As[aKq[l]*4+1][aRow[l]] = v.y;
            As[aKq[l]*4+2][aRow[l]] = v.z;
            As[aKq[l]*4+3][aRow[l]] = v.w;
        }
        #pragma unroll
        for (int l = 0; l < BL; l++)
            *(float4*)&Bs[bKk[l]][bNq[l]*4] = rB[l];
        __syncthreads();
        if (k0 + BK < K) loadTile(k0 + BK);
        #pragma unroll
        for (int kk = 0; kk < BK; kk++) {
            u64 a2[TM/2];
            #pragma unroll
            for (int u = 0; u < TM/2; u++)
                a2[u] = *(const u64*)&As[kk][ty*TM + 2*u];
            float bf[TN];
            #pragma unroll
            for (int jq = 0; jq < TN/4; jq++) {
                float4 bv = *(const float4*)&Bs[kk][tx*TN + jq*4];
                bf[jq*4+0] = bv.x; bf[jq*4+1] = bv.y;
                bf[jq*4+2] = bv.z; bf[jq*4+3] = bv.w;
            }
            #pragma unroll
            for (int j = 0; j < TN; j++) {
                u64 bb = pack2(bf[j], bf[j]);
                #pragma unroll
                for (int u = 0; u < TM/2; u++)
                    ffma2(acc2[u][j], a2[u], bb);
            }
        }
    }

    #pragma unroll
    for (int u = 0; u < TM/2; u++) {
        int gr0 = mBase + ty*TM + 2*u;
        int gr1 = gr0 + 1;
        #pragma unroll
        for (int j = 0; j < TN; j++) {
            int col = nBase + tx*TN + j;
            float2 v = unpack2(acc2[u][j]);
            float bb = g.bias[col];
            float x = v.x + bb, y = v.y + bb;
            if (MODE == 2) {
                x = (x > 0.f) ? x : (__expf(x) - 1.f);
                y = (y > 0.f) ? y : (__expf(y) - 1.f);
            }
            if (gr0 < M) g.C[(size_t)gr0*N + col] = x;
            if (gr1 < M) g.C[(size_t)gr1*N + col] = y;
        }
    }
}

// ---------------- final logits at target rows ----------------
__global__ __launch_bounds__(256)
void final_kernel(const float* __restrict__ st0, const float* __restrict__ st1,
                  const float* __restrict__ betaPtr,
                  const float* __restrict__ lW1, const float* __restrict__ lb1,
                  const int* __restrict__ tgt, float* __restrict__ out) {
    int t    = blockIdx.x;
    int col  = threadIdx.x >> 5;
    int lane = threadIdx.x & 31;
    int n = tgt[t];
    float b0 = betaPtr[0], b1 = betaPtr[1];
    float acc = 0.f;
    for (int k = lane; k < HDIM; k += 32) {
        float a = b0*st0[(size_t)n*HDIM + k] + b1*st1[(size_t)n*HDIM + k];
        acc += a * lW1[(size_t)k*COUT + col];
    }
    #pragma unroll
    for (int o = 16; o > 0; o >>= 1) acc += __shfl_xor_sync(0xffffffffu, acc, o);
    if (lane == 0) out[(size_t)t*COUT + col] = acc + lb1[col];
}

// ---------------- host orchestration ----------------
extern "C" void kernel_launch(void* const* d_in, const int* in_sizes, int n_in,
                              void* d_out, int out_size) {
    const float* X0   = (const float*)d_in[0];
    const float* X1   = (const float*)d_in[1];
    const float* X2   = (const float*)d_in[2];
    const float* fcW[3] = {(const float*)d_in[3], (const float*)d_in[5], (const float*)d_in[7]};
    const float* fcb[3] = {(const float*)d_in[4], (const float*)d_in[6], (const float*)d_in[8]};
    const float* attn1 = (const float*)d_in[9];
    const float* attn2 = (const float*)d_in[10];
    const float* mpW   = (const float*)d_in[11];
    const float* mpb   = (const float*)d_in[12];
    const float* mpq   = (const float*)d_in[13];
    const float* lW0   = (const float*)d_in[14];
    const float* lb0   = (const float*)d_in[15];
    const float* lW1   = (const float*)d_in[16];
    const float* lb1   = (const float*)d_in[17];
    const int*   mpidx = (const int*)d_in[18];
    const int*   tgt   = (const int*)d_in[19];
    float* out = (float*)d_out;

    float *h0, *h1, *stb, *sp, *bp;
    __nv_bfloat16* btp;
    int *cnt, *ofs, *cur;
    cudaGetSymbolAddress((void**)&h0,  g_h0);
    cudaGetSymbolAddress((void**)&h1,  g_h1);
    cudaGetSymbolAddress((void**)&stb, g_st);
    cudaGetSymbolAddress((void**)&sp,  g_s);
    cudaGetSymbolAddress((void**)&bp,  g_beta);
    cudaGetSymbolAddress((void**)&cnt, g_counts);
    cudaGetSymbolAddress((void**)&ofs, g_ofs);
    cudaGetSymbolAddress((void**)&cur, g_cursor);
    cudaGetSymbolAddress((void**)&btp, g_bt);

    const size_t SLABST = (size_t)NTn*HDIM;
    const int mTiles = (NTn + 127) / 128;

    zero_i_kernel<<<(NSLAB*NTn + 255)/256, 256>>>(cnt, NSLAB*NTn);

    // per-type feature FC -> h0 (batched z=3)
    {
        GArgsN ga = {};
        const float* Xs[3] = {X0, X1, X2};
        const int    Ks[3] = {512, 256, 128};
        for (int i = 0; i < NTYPES; i++) {
            ga.z[i].A0 = Xs[i]; ga.z[i].B = fcW[i]; ga.z[i].bias = fcb[i];
            ga.z[i].C  = h0 + (size_t)i*NTn*DD; ga.z[i].K = Ks[i];
        }
        gemm_kernel<128,64,16,8,4,0><<<dim3(1, mTiles, NTYPES), 256>>>(NTn, DD, ga);
    }

    // CSR build + mpW transpose (layer-invariant)
    hist_kernel   <<<dim3((ECNT+255)/256, 1, NSLAB), 256>>>(mpidx, cnt);
    scan_kernel   <<<NSLAB, 1024>>>(cnt, ofs, cur);
    scatter_kernel<<<dim3((ECNT+255)/256, 1, NSLAB), 256>>>(mpidx, cur);
    transW_kernel <<<dim3((AVd*HDIM+255)/256, 1, NTYPES+1), 256>>>(mpW);

    for (int l = 0; l < 2; l++) {
        const float* hin = (l == 0) ? h0 : h1;
        int nslab  = (l == 0) ? NSLAB : NMP;     // layer 1: only type 0
        int ntypes = (l == 0) ? NTYPES : 1;

        dot_kernel <<<dim3((NNODES+7)/8, 1, nslab), 256>>>(hin, attn1, attn2, l*NSLAB);
        edge_kernel<<<dim3((ECNT+255)/256, 1, nslab), 256>>>();
        node_kernel<<<dim3((NTn+7)/8, 1, nslab), 256>>>(hin);

        zero_s_kernel<<<1, 32>>>();
        {
            T1ArgsN ga = {};
            for (int zz = 0; zz < nslab; zz++) {
                int type = (l == 0) ? (zz / NMP) : 0;
                int mi = (l == 0) ? type : NTYPES;       // transposed-matrix index
                int bi = l*NTYPES + type;                // bias/q index
                ga.z[zz].A    = stb + (size_t)zz*SLABST;
                ga.z[zz].Bt   = btp + (size_t)mi*AVd*HDIM;
                ga.z[zz].bias = mpb + (size_t)bi*AVd;
                ga.z[zz].q    = mpq + (size_t)bi*AVd;
                ga.z[zz].sOut = sp + zz;
            }
            mp_attn_kernel<<<dim3(mTiles, 1, nslab), 256>>>(NTn, ga);
        }
        beta_kernel<<<1, 32>>>(ntypes);

        if (l == 0) {
            GArgsN ga = {};
            for (int t = 0; t < NTYPES; t++) {
                ga.z[t].A0 = stb + (size_t)(t*2+0)*SLABST;
                ga.z[t].A1 = stb + (size_t)(t*2+1)*SLABST;
                ga.z[t].beta2 = bp + t*2;
                ga.z[t].B = lW0; ga.z[t].bias = lb0;
                ga.z[t].C = h1 + (size_t)t*NTn*DD;
                ga.z[t].K = HDIM;
            }
            gemm_kernel<128,64,16,8,4,2><<<dim3(1, mTiles, NTYPES), 256>>>(NTn, DD, ga);
        } else {
            final_kernel<<<NTGTn, 256>>>(stb, stb + SLABST, bp, lW1, lb1, tgt, out);
        }
    }
}

// round 6
// speedup vs baseline: 2.5196x; 1.1369x over previous
#include <cuda_runtime.h>
#include <cuda_bf16.h>
#include <math.h>
#include <stdint.h>

#define NTn     34000
#define NTYPES  3
#define NMP     2
#define ECNT    300000
#define HH      8
#define DD      64
#define HDIM    512
#define AVd     128
#define COUT    8
#define NTGTn   1000
#define NNODES  (NTYPES*NTn)
#define NSLAB   (NTYPES*NMP)

// ---------------- scratch (device globals; no allocation) ----------------
__device__ float g_h0[(size_t)NNODES*DD];
__device__ float g_h1[(size_t)NNODES*DD];
__device__ float g_e [(size_t)NSLAB*ECNT*HH];
__device__ float g_st[(size_t)NSLAB*NTn*HDIM];
__device__ float g_u [(size_t)NSLAB*NTn*HH];
__device__ float g_t2[(size_t)NSLAB*NNODES*HH];
__device__ int4  g_srt[(size_t)NSLAB*ECNT];
__device__ int   g_counts[NSLAB*NTn];
__device__ int   g_ofs   [NSLAB*NTn];
__device__ int   g_cursor[NSLAB*NTn];
__device__ float g_s[NSLAB];
__device__ __nv_bfloat16 g_bt[(size_t)(NTYPES+1)*AVd*HDIM];  // mpW^T bf16
// split-bf16 transposed weights [64][K]: fc0(K512), fc1(K256), fc2(K128), lW0(K512)
#define WOFF0 0
#define WOFF1 (64*512)
#define WOFF2 (WOFF1 + 64*256)
#define WOFF3 (WOFF2 + 64*128)
#define WTOT  (WOFF3 + 64*512)
__device__ __nv_bfloat16 g_wb[WTOT];
__device__ __nv_bfloat16 g_ws[WTOT];

__device__ __forceinline__ float tanh_apx(float x) {
    float y; asm("tanh.approx.f32 %0, %1;" : "=f"(y) : "f"(x)); return y;
}
__device__ __forceinline__ uint32_t smem_u32(const void* p) {
    uint32_t a;
    asm("{ .reg .u64 t; cvta.to.shared.u64 t, %1; cvt.u32.u64 %0, t; }"
        : "=r"(a) : "l"(p));
    return a;
}

// ---------------- small utility kernels ----------------
__global__ void zero_i_kernel(int* p, int n) {
    int i = blockIdx.x*blockDim.x + threadIdx.x;
    if (i < n) p[i] = 0;
}
// transpose mpW [mi][HDIM][AVd] -> bf16 [mi][AVd][HDIM]
__global__ void transW_kernel(const float* __restrict__ mpW) {
    int mi = blockIdx.z;
    int t = blockIdx.x*256 + threadIdx.x;
    if (t < AVd*HDIM) {
        int n = t >> 9;
        int k = t & 511;
        float v = mpW[(size_t)mi*HDIM*AVd + (size_t)k*AVd + n];
        g_bt[(size_t)mi*AVd*HDIM + (size_t)n*HDIM + k] = __float2bfloat16(v);
    }
}
// split-transpose W [K][64] -> big/small bf16 [64][K]
struct PArgs { const float* W; int K; int off; };
struct PArgs4 { PArgs z[4]; };
__global__ void prepW_kernel(PArgs4 pa) {
    PArgs g = pa.z[blockIdx.z];
    int idx = blockIdx.x*256 + threadIdx.x;
    if (idx < 64*g.K) {
        int n = idx & 63;
        int k = idx >> 6;
        float v = g.W[(size_t)k*64 + n];
        __nv_bfloat16 big = __float2bfloat16_rn(v);
        float r = v - __bfloat162float(big);
        g_wb[g.off + (size_t)n*g.K + k] = big;
        g_ws[g.off + (size_t)n*g.K + k] = __float2bfloat16_rn(r);
    }
}

// ---------------- CSR construction ----------------
__global__ void hist_kernel(const int* __restrict__ mpidx, int* __restrict__ counts) {
    int slab = blockIdx.z;
    int e = blockIdx.x*blockDim.x + threadIdx.x;
    if (e < ECNT) {
        int dst = mpidx[(size_t)slab*ECNT*3 + e*3] - (slab/NMP)*NTn;
        atomicAdd(&counts[(size_t)slab*NTn + dst], 1);
    }
}

__global__ void scan_kernel(const int* __restrict__ countsAll,
                            int* __restrict__ ofsAll, int* __restrict__ cursorAll) {
    int slab = blockIdx.x;
    const int4* counts4 = (const int4*)(countsAll + (size_t)slab*NTn);
    int4* ofs4    = (int4*)(ofsAll    + (size_t)slab*NTn);
    int4* cursor4 = (int4*)(cursorAll + (size_t)slab*NTn);
    const int N4 = NTn/4;
    __shared__ int warp_sums[32];
    __shared__ int s_carry;
    if (threadIdx.x == 0) s_carry = 0;
    __syncthreads();
    int lane = threadIdx.x & 31, wid = threadIdx.x >> 5;
    for (int base = 0; base < N4; base += 1024) {
        int i4 = base + threadIdx.x;
        int4 v = (i4 < N4) ? counts4[i4] : make_int4(0,0,0,0);
        int c1 = v.x, c2 = c1 + v.y, c3 = c2 + v.z, c4 = c3 + v.w;
        int tot = c4;
        int incl = tot;
        #pragma unroll
        for (int d = 1; d < 32; d <<= 1) {
            int t = __shfl_up_sync(0xffffffffu, incl, d);
            if (lane >= d) incl += t;
        }
        if (lane == 31) warp_sums[wid] = incl;
        __syncthreads();
        if (wid == 0) {
            int w = warp_sums[lane];
            #pragma unroll
            for (int d = 1; d < 32; d <<= 1) {
                int t = __shfl_up_sync(0xffffffffu, w, d);
                if (lane >= d) w += t;
            }
            warp_sums[lane] = w;
        }
        __syncthreads();
        int add = s_carry + (wid > 0 ? warp_sums[wid-1] : 0);
        int be  = add + incl - tot;
        if (i4 < N4) {
            int4 o = make_int4(be, be + c1, be + c2, be + c3);
            ofs4[i4] = o;
            cursor4[i4] = o;
        }
        __syncthreads();
        if (threadIdx.x == 1023) s_carry = add + incl;
        __syncthreads();
    }
}

__global__ void scatter_kernel(const int* __restrict__ mpidx, int* __restrict__ cursorAll) {
    int slab = blockIdx.z;
    int e = blockIdx.x*blockDim.x + threadIdx.x;
    if (e < ECNT) {
        const int* mp = mpidx + (size_t)slab*ECNT*3 + (size_t)e*3;
        int n0 = mp[0], n1 = mp[1], n2 = mp[2];
        int dst = n0 - (slab/NMP)*NTn;
        int pos = atomicAdd(&cursorAll[(size_t)slab*NTn + dst], 1);
        g_srt[(size_t)slab*ECNT + pos] = make_int4(n0, n1, n2, 0);
    }
}

// ---------------- per-node attention dots (warp/node, both metapaths of a type) ----
__global__ __launch_bounds__(256)
void dot_kernel(const float* __restrict__ h, const float* __restrict__ attn1,
                const float* __restrict__ attn2, int layerOff) {
    int type = blockIdx.z;
    size_t base = (size_t)(layerOff + type*NMP)*HH*DD;
    __shared__ float a1s[NMP*HH*DD];
    __shared__ float a2s[NMP*HH*DD];
    for (int i = threadIdx.x; i < NMP*HH*DD; i += blockDim.x) {
        a1s[i] = attn1[base + i];
        a2s[i] = attn2[base + i];
    }
    // fold g_s zeroing into this kernel (runs before mp_attn each layer)
    if (blockIdx.x == 0 && blockIdx.z == 0 && threadIdx.x < NSLAB)
        g_s[threadIdx.x] = 0.f;
    __syncthreads();
    int lane = threadIdx.x & 31;
    int wid  = threadIdx.x >> 5;
    int gn = blockIdx.x*8 + wid;
    if (gn >= NNODES) return;

    float hv0 = h[(size_t)gn*DD + lane];
    float hv1 = h[(size_t)gn*DD + 32 + lane];
    int ibase = type*NTn;
    bool isdst = (gn >= ibase) && (gn < ibase + NTn);
    const float third = 1.f/3.f;

    #pragma unroll
    for (int p = 0; p < NMP; p++) {
        int slab = type*NMP + p;
        const float* a2p = a2s + p*HH*DD;
        const float* a1p = a1s + p*HH*DD;
        float r2[HH], r1[HH];
        #pragma unroll
        for (int hh = 0; hh < HH; hh++) {
            float v = hv0*a2p[hh*DD+lane] + hv1*a2p[hh*DD+32+lane];
            #pragma unroll
            for (int o = 16; o > 0; o >>= 1) v += __shfl_xor_sync(0xffffffffu, v, o);
            r2[hh] = v;
        }
        if (isdst) {
            #pragma unroll
            for (int hh = 0; hh < HH; hh++) {
                float v = hv0*a1p[hh*DD+lane] + hv1*a1p[hh*DD+32+lane];
                #pragma unroll
                for (int o = 16; o > 0; o >>= 1) v += __shfl_xor_sync(0xffffffffu, v, o);
                r1[hh] = v;
            }
        }
        float myt2 = 0.f, myu = 0.f;
        #pragma unroll
        for (int hh = 0; hh < HH; hh++) {
            if (lane == hh) {
                myt2 = r2[hh];
                if (isdst) myu = r1[hh] + r2[hh]*third;
            }
        }
        if (lane < HH) {
            g_t2[((size_t)slab*NNODES + gn)*HH + lane] = myt2;
            if (isdst) g_u[((size_t)slab*NTn + (gn - ibase))*HH + lane] = myu;
        }
    }
}

// ---------------- per-edge logits from precomputed dots ----------------
__global__ __launch_bounds__(256)
void edge_kernel() {
    int slab = blockIdx.z;
    size_t eb = (size_t)slab*ECNT;
    int e = blockIdx.x*256 + threadIdx.x;
    if (e >= ECNT) return;
    int4 tr = g_srt[eb + e];
    int ibase = (slab/NMP)*NTn;
    const float* up  = g_u  + ((size_t)slab*NTn + (tr.x - ibase))*HH;
    const float* t2b = g_t2 + (size_t)slab*NNODES*HH;
    float4 u0 = *(const float4*)(up);
    float4 u1 = *(const float4*)(up + 4);
    float4 p0 = *(const float4*)(t2b + (size_t)tr.y*HH);
    float4 p1 = *(const float4*)(t2b + (size_t)tr.y*HH + 4);
    float4 q0 = *(const float4*)(t2b + (size_t)tr.z*HH);
    float4 q1 = *(const float4*)(t2b + (size_t)tr.z*HH + 4);
    const float third = 1.f/3.f;
    float ev[HH];
    ev[0] = u0.x + (p0.x+q0.x)*third;  ev[1] = u0.y + (p0.y+q0.y)*third;
    ev[2] = u0.z + (p0.z+q0.z)*third;  ev[3] = u0.w + (p0.w+q0.w)*third;
    ev[4] = u1.x + (p1.x+q1.x)*third;  ev[5] = u1.y + (p1.y+q1.y)*third;
    ev[6] = u1.z + (p1.z+q1.z)*third;  ev[7] = u1.w + (p1.w+q1.w)*third;
    #pragma unroll
    for (int hh = 0; hh < HH; hh++)
        ev[hh] = (ev[hh] > 0.f) ? ev[hh] : 0.2f*ev[hh];
    float* dst = g_e + (eb + (size_t)e)*HH;
    *(float4*)(dst)     = make_float4(ev[0], ev[1], ev[2], ev[3]);
    *(float4*)(dst + 4) = make_float4(ev[4], ev[5], ev[6], ev[7]);
}

// ---------------- segment softmax + weighted sum (warp per node) ----------------
__global__ __launch_bounds__(256)
void node_kernel(const float* __restrict__ h) {
    int slab = blockIdx.z;
    const int*  ofs = g_ofs + (size_t)slab*NTn;
    const int4* srt = g_srt + (size_t)slab*ECNT;
    const float* eArr = g_e + (size_t)slab*ECNT*HH;
    float* st = g_st + (size_t)slab*NTn*HDIM;

    int lane = threadIdx.x & 31;
    int wid  = threadIdx.x >> 5;
    int n = blockIdx.x*8 + wid;
    if (n >= NTn) return;

    int s0 = ofs[n];
    int s1 = (n < NTn-1) ? ofs[n+1] : ECNT;
    if (s1 == s0) {
        #pragma unroll
        for (int hh = 0; hh < HH; hh++) {
            st[(size_t)n*HDIM + hh*DD + lane]      = 0.f;
            st[(size_t)n*HDIM + hh*DD + 32 + lane] = 0.f;
        }
        return;
    }
    int ibase = (slab/NMP)*NTn;

    float mh[HH];
    #pragma unroll
    for (int hh = 0; hh < HH; hh++) mh[hh] = -3.402823466e38f;
    for (int j = s0 + lane; j < s1; j += 32) {
        float4 e0 = *(const float4*)(eArr + (size_t)j*HH);
        float4 e1 = *(const float4*)(eArr + (size_t)j*HH + 4);
        mh[0]=fmaxf(mh[0],e0.x); mh[1]=fmaxf(mh[1],e0.y);
        mh[2]=fmaxf(mh[2],e0.z); mh[3]=fmaxf(mh[3],e0.w);
        mh[4]=fmaxf(mh[4],e1.x); mh[5]=fmaxf(mh[5],e1.y);
        mh[6]=fmaxf(mh[6],e1.z); mh[7]=fmaxf(mh[7],e1.w);
    }
    #pragma unroll
    for (int hh = 0; hh < HH; hh++) {
        #pragma unroll
        for (int o = 16; o > 0; o >>= 1)
            mh[hh] = fmaxf(mh[hh], __shfl_xor_sync(0xffffffffu, mh[hh], o));
    }
    float myM = 0.f;
    #pragma unroll
    for (int hh = 0; hh < HH; hh++) if (lane == hh) myM = mh[hh];

    float den = 0.f;
    float acc[2*HH];
    #pragma unroll
    for (int k = 0; k < 2*HH; k++) acc[k] = 0.f;

    for (int j = s0; j < s1; j += 4) {
        int m = s1 - j; if (m > 4) m = 4;
        int nn1[4], nn2[4];
        #pragma unroll
        for (int c = 0; c < 4; c++) {
            int jj = j + ((c < m) ? c : 0);
            int4 tr = srt[jj];
            nn1[c] = tr.y; nn2[c] = tr.z;
        }
        float exv[4];
        #pragma unroll
        for (int c = 0; c < 4; c++) {
            float evl = 0.f;
            if (lane < HH && c < m)
                evl = __expf(eArr[(size_t)(j+c)*HH + lane] - myM);
            exv[c] = evl;
            den += evl;
        }
        float f1a[4], f1b[4], f2a[4], f2b[4];
        #pragma unroll
        for (int c = 0; c < 4; c++) {
            f1a[c] = h[(size_t)nn1[c]*DD + lane];
            f1b[c] = h[(size_t)nn1[c]*DD + 32 + lane];
            f2a[c] = h[(size_t)nn2[c]*DD + lane];
            f2b[c] = h[(size_t)nn2[c]*DD + 32 + lane];
        }
        #pragma unroll
        for (int c = 0; c < 4; c++) {
            float sa = f1a[c] + f2a[c];
            float sb = f1b[c] + f2b[c];
            #pragma unroll
            for (int hh = 0; hh < HH; hh++) {
                float exh = __shfl_sync(0xffffffffu, exv[c], hh);
                acc[hh*2+0] += exh * sa;
                acc[hh*2+1] += exh * sb;
            }
        }
    }

    float hn0a = h[(size_t)(ibase+n)*DD + lane];
    float hn0b = h[(size_t)(ibase+n)*DD + 32 + lane];
    const float third = 1.f/3.f;
    #pragma unroll
    for (int hh = 0; hh < HH; hh++) {
        float dh = __shfl_sync(0xffffffffu, den, hh);
        float inv = 1.f / dh;
        float v0 = (hn0a + acc[hh*2+0]*inv) * third;
        float v1 = (hn0b + acc[hh*2+1]*inv) * third;
        v0 = (v0 > 0.f) ? v0 : (__expf(v0) - 1.f);
        v1 = (v1 > 0.f) ? v1 : (__expf(v1) - 1.f);
        st[(size_t)n*HDIM + hh*DD + lane]      = v0;
        st[(size_t)n*HDIM + hh*DD + 32 + lane] = v1;
    }
}

// ---------------- HMMA bf16 mode-1 GEMM: s += sum_rows(tanh(A@B^T + bias).q) ----
struct T1Args { const float* A; const __nv_bfloat16* Bt;
                const float* bias; const float* q; float* sOut; };
struct T1ArgsN { T1Args z[NSLAB]; };

__global__ __launch_bounds__(256)
void mp_attn_kernel(int M, T1ArgsN ga) {
    constexpr int AP = 72;
    __shared__ __align__(16) __nv_bfloat16 As[128*AP];
    __shared__ __align__(16) __nv_bfloat16 Bs[128*AP];
    __shared__ float sb_bias[128], sb_q[128];
    __shared__ float red[256];
    const T1Args g = ga.z[blockIdx.z];
    const int tid  = threadIdx.x;
    const int wid  = tid >> 5;
    const int lane = tid & 31;
    const int mBase = blockIdx.x * 128;
    const int wm = (wid >> 2) * 64;
    const int wn = (wid & 3) * 32;

    if (tid < 128) { sb_bias[tid] = g.bias[tid]; sb_q[tid] = g.q[tid]; }

    float d[4][4][4];
    #pragma unroll
    for (int mt = 0; mt < 4; mt++)
        #pragma unroll
        for (int nt = 0; nt < 4; nt++)
            #pragma unroll
            for (int f = 0; f < 4; f++) d[mt][nt][f] = 0.f;

    float4 ra[8]; uint4 rb[4];
    int aRow[8], aCol[8], bRow[4], bCol[4];
    #pragma unroll
    for (int i = 0; i < 8; i++) {
        int t = tid + i*256;
        aRow[i] = t >> 4;
        aCol[i] = (t & 15) * 4;
    }
    #pragma unroll
    for (int i = 0; i < 4; i++) {
        int t = tid + i*256;
        bRow[i] = t >> 3;
        bCol[i] = (t & 7) * 8;
    }

    auto loadRegs = [&](int c) {
        #pragma unroll
        for (int i = 0; i < 8; i++) {
            int gr = mBase + aRow[i];
            ra[i] = (gr < M)
                ? *(const float4*)(g.A + (size_t)gr*HDIM + c*64 + aCol[i])
                : make_float4(0.f, 0.f, 0.f, 0.f);
        }
        #pragma unroll
        for (int i = 0; i < 4; i++)
            rb[i] = *(const uint4*)(g.Bt + (size_t)bRow[i]*HDIM + c*64 + bCol[i]);
    };
    auto storeSmem = [&]() {
        #pragma unroll
        for (int i = 0; i < 8; i++) {
            __nv_bfloat162 p0 = __floats2bfloat162_rn(ra[i].x, ra[i].y);
            __nv_bfloat162 p1 = __floats2bfloat162_rn(ra[i].z, ra[i].w);
            uint2 u;
            u.x = *(uint32_t*)&p0;
            u.y = *(uint32_t*)&p1;
            *(uint2*)&As[aRow[i]*AP + aCol[i]] = u;
        }
        #pragma unroll
        for (int i = 0; i < 4; i++)
            *(uint4*)&Bs[bRow[i]*AP + bCol[i]] = rb[i];
    };

    uint32_t aSb = smem_u32(As);
    uint32_t bSb = smem_u32(Bs);

    loadRegs(0);
    #pragma unroll 1
    for (int c = 0; c < 8; c++) {
        storeSmem();
        __syncthreads();
        if (c < 7) loadRegs(c + 1);
        #pragma unroll
        for (int ks = 0; ks < 4; ks++) {
            uint32_t af[4][4];
            #pragma unroll
            for (int mt = 0; mt < 4; mt++) {
                uint32_t addr = aSb +
                    (((wm + mt*16 + (lane & 15))*AP + ks*16 + (lane >> 4)*8) << 1);
                asm volatile("ldmatrix.sync.aligned.m8n8.x4.shared.b16 {%0,%1,%2,%3}, [%4];"
                    : "=r"(af[mt][0]), "=r"(af[mt][1]), "=r"(af[mt][2]), "=r"(af[mt][3])
                    : "r"(addr));
            }
            uint32_t bf[4][2];
            #pragma unroll
            for (int nt = 0; nt < 4; nt++) {
                uint32_t addr = bSb +
                    (((wn + nt*8 + (lane & 7))*AP + ks*16 + ((lane >> 3) & 1)*8) << 1);
                asm volatile("ldmatrix.sync.aligned.m8n8.x2.shared.b16 {%0,%1}, [%2];"
                    : "=r"(bf[nt][0]), "=r"(bf[nt][1])
                    : "r"(addr));
            }
            #pragma unroll
            for (int mt = 0; mt < 4; mt++)
                #pragma unroll
                for (int nt = 0; nt < 4; nt++)
                    asm volatile(
                        "mma.sync.aligned.m16n8k16.row.col.f32.bf16.bf16.f32 "
                        "{%0,%1,%2,%3}, {%4,%5,%6,%7}, {%8,%9}, {%0,%1,%2,%3};"
                        : "+f"(d[mt][nt][0]), "+f"(d[mt][nt][1]),
                          "+f"(d[mt][nt][2]), "+f"(d[mt][nt][3])
                        : "r"(af[mt][0]), "r"(af[mt][1]), "r"(af[mt][2]), "r"(af[mt][3]),
                          "r"(bf[nt][0]), "r"(bf[nt][1]));
        }
        __syncthreads();
    }

    int g8  = lane >> 2;
    int tig = lane & 3;
    float local = 0.f;
    #pragma unroll
    for (int mt = 0; mt < 4; mt++) {
        int r0 = mBase + wm + mt*16 + g8;
        int r1 = r0 + 8;
        #pragma unroll
        for (int nt = 0; nt < 4; nt++) {
            int c0 = wn + nt*8 + 2*tig;
            float b0v = sb_bias[c0],   q0v = sb_q[c0];
            float b1v = sb_bias[c0+1], q1v = sb_q[c0+1];
            if (r0 < M)
                local += tanh_apx(d[mt][nt][0] + b0v)*q0v
                       + tanh_apx(d[mt][nt][1] + b1v)*q1v;
            if (r1 < M)
                local += tanh_apx(d[mt][nt][2] + b0v)*q0v
                       + tanh_apx(d[mt][nt][3] + b1v)*q1v;
        }
    }
    red[tid] = local;
    __syncthreads();
    if (tid < 128) red[tid] += red[tid + 128];
    __syncthreads();
    if (tid < 64) red[tid] += red[tid + 64];
    __syncthreads();
    if (tid < 32) {
        float v = red[tid] + red[tid + 32];
        #pragma unroll
        for (int o = 16; o > 0; o >>= 1) v += __shfl_xor_sync(0xffffffffu, v, o);
        if (tid == 0) atomicAdd(g.sOut, v);
    }
}

// ---------------- split-bf16 HMMA GEMM (exact-ish fp32): N=64 ----------------
// MODE 0: C = A0 @ W + bias       MODE 2: C = elu( (b0*A0 + b1*A1) @ W + bias )
// W given as transposed bf16 big/small pairs [64][K]; D = AbBb + AbBs + AsBb.
struct HArgs { const float* A0; const float* A1;
               const __nv_bfloat16* Bb; const __nv_bfloat16* Bs2;
               const float* bias; float* C; int K; int sIdx; };
struct HArgsN { HArgs z[NTYPES]; };

template<int MODE>
__global__ __launch_bounds__(256)
void hgemm_kernel(int M, HArgsN ga) {
    constexpr int AP = 72;
    __shared__ __align__(16) __nv_bfloat16 AsB[128*AP];
    __shared__ __align__(16) __nv_bfloat16 AsS[128*AP];
    __shared__ __align__(16) __nv_bfloat16 BsB[64*AP];
    __shared__ __align__(16) __nv_bfloat16 BsS[64*AP];
    __shared__ float sb_bias[64];
    __shared__ float sb_beta[2];
    const HArgs g = ga.z[blockIdx.z];
    const int tid  = threadIdx.x;
    const int wid  = tid >> 5;
    const int lane = tid & 31;
    const int mBase = blockIdx.x * 128;
    const int wm = (wid >> 1) * 32;   // 4 M-warps x 32
    const int wn = (wid & 1) * 32;    // 2 N-warps x 32
    const int K = g.K;

    if (tid < 64) sb_bias[tid] = g.bias[tid];
    if (MODE == 2 && tid == 0) {
        float s0 = g_s[g.sIdx]   * (1.f/(float)NTn);
        float s1 = g_s[g.sIdx+1] * (1.f/(float)NTn);
        float mm = fmaxf(s0, s1);
        float e0 = expf(s0 - mm), e1 = expf(s1 - mm);
        sb_beta[0] = e0 / (e0 + e1);
        sb_beta[1] = e1 / (e0 + e1);
    }
    __syncthreads();
    float cb0 = 0.f, cb1 = 0.f;
    if (MODE == 2) { cb0 = sb_beta[0]; cb1 = sb_beta[1]; }

    float d[2][4][4];
    #pragma unroll
    for (int mt = 0; mt < 2; mt++)
        #pragma unroll
        for (int nt = 0; nt < 4; nt++)
            #pragma unroll
            for (int f = 0; f < 4; f++) d[mt][nt][f] = 0.f;

    // A: 128x64 fp32 per chunk -> 8 float4/thread. B: 64x64 bf16 pair -> 2 uint4 each.
    float4 ra0[8], ra1[8]; uint4 rbb[2], rbs[2];
    int aRow[8], aCol[8], bRow[2], bCol[2];
    #pragma unroll
    for (int i = 0; i < 8; i++) {
        int t = tid + i*256;
        aRow[i] = t >> 4;
        aCol[i] = (t & 15) * 4;
    }
    #pragma unroll
    for (int i = 0; i < 2; i++) {
        int t = tid + i*256;
        bRow[i] = t >> 3;
        bCol[i] = (t & 7) * 8;
    }

    auto loadRegs = [&](int c) {
        #pragma unroll
        for (int i = 0; i < 8; i++) {
            int gr = mBase + aRow[i];
            float4 v = make_float4(0.f,0.f,0.f,0.f);
            float4 w = make_float4(0.f,0.f,0.f,0.f);
            if (gr < M) {
                v = *(const float4*)(g.A0 + (size_t)gr*K + c*64 + aCol[i]);
                if (MODE == 2)
                    w = *(const float4*)(g.A1 + (size_t)gr*K + c*64 + aCol[i]);
            }
            ra0[i] = v;
            if (MODE == 2) ra1[i] = w;
        }
        #pragma unroll
        for (int i = 0; i < 2; i++) {
            rbb[i] = *(const uint4*)(g.Bb  + (size_t)bRow[i]*K + c*64 + bCol[i]);
            rbs[i] = *(const uint4*)(g.Bs2 + (size_t)bRow[i]*K + c*64 + bCol[i]);
        }
    };
    auto storeSmem = [&]() {
        #pragma unroll
        for (int i = 0; i < 8; i++) {
            float4 v = ra0[i];
            if (MODE == 2) {
                float4 w = ra1[i];
                v.x = cb0*v.x + cb1*w.x;  v.y = cb0*v.y + cb1*w.y;
                v.z = cb0*v.z + cb1*w.z;  v.w = cb0*v.w + cb1*w.w;
            }
            __nv_bfloat16 bx = __float2bfloat16_rn(v.x);
            __nv_bfloat16 by = __float2bfloat16_rn(v.y);
            __nv_bfloat16 bz = __float2bfloat16_rn(v.z);
            __nv_bfloat16 bw = __float2bfloat16_rn(v.w);
            __nv_bfloat16 sx = __float2bfloat16_rn(v.x - __bfloat162float(bx));
            __nv_bfloat16 sy = __float2bfloat16_rn(v.y - __bfloat162float(by));
            __nv_bfloat16 sz = __float2bfloat16_rn(v.z - __bfloat162float(bz));
            __nv_bfloat16 sw = __float2bfloat16_rn(v.w - __bfloat162float(bw));
            __nv_bfloat162 pb0 = __halves2bfloat162(bx, by);
            __nv_bfloat162 pb1 = __halves2bfloat162(bz, bw);
            __nv_bfloat162 ps0 = __halves2bfloat162(sx, sy);
            __nv_bfloat162 ps1 = __halves2bfloat162(sz, sw);
            uint2 ub, us;
            ub.x = *(uint32_t*)&pb0;  ub.y = *(uint32_t*)&pb1;
            us.x = *(uint32_t*)&ps0;  us.y = *(uint32_t*)&ps1;
            *(uint2*)&AsB[aRow[i]*AP + aCol[i]] = ub;
            *(uint2*)&AsS[aRow[i]*AP + aCol[i]] = us;
        }
        #pragma unroll
        for (int i = 0; i < 2; i++) {
            *(uint4*)&BsB[bRow[i]*AP + bCol[i]] = rbb[i];
            *(uint4*)&BsS[bRow[i]*AP + bCol[i]] = rbs[i];
        }
    };

    uint32_t aBb = smem_u32(AsB), aSb = smem_u32(AsS);
    uint32_t bBb = smem_u32(BsB), bSb = smem_u32(BsS);

    const int chunks = K >> 6;
    loadRegs(0);
    #pragma unroll 1
    for (int c = 0; c < chunks; c++) {
        storeSmem();
        __syncthreads();
        if (c + 1 < chunks) loadRegs(c + 1);
        #pragma unroll
        for (int ks = 0; ks < 4; ks++) {
            uint32_t afB[2][4], afS[2][4];
            #pragma unroll
            for (int mt = 0; mt < 2; mt++) {
                uint32_t off = ((wm + mt*16 + (lane & 15))*AP + ks*16 + (lane >> 4)*8) << 1;
                asm volatile("ldmatrix.sync.aligned.m8n8.x4.shared.b16 {%0,%1,%2,%3}, [%4];"
                    : "=r"(afB[mt][0]), "=r"(afB[mt][1]), "=r"(afB[mt][2]), "=r"(afB[mt][3])
                    : "r"(aBb + off));
                asm volatile("ldmatrix.sync.aligned.m8n8.x4.shared.b16 {%0,%1,%2,%3}, [%4];"
                    : "=r"(afS[mt][0]), "=r"(afS[mt][1]), "=r"(afS[mt][2]), "=r"(afS[mt][3])
                    : "r"(aSb + off));
            }
            // B frags: x4 over 16 rows covers 2 n8 tiles: {r0,r2} and {r1,r3}
            uint32_t bfB[4][2], bfS[4][2];
            #pragma unroll
            for (int ntp = 0; ntp < 2; ntp++) {
                uint32_t off = ((wn + ntp*16 + (lane & 15))*AP + ks*16 + (lane >> 4)*8) << 1;
                uint32_t r0, r1, r2, r3;
                asm volatile("ldmatrix.sync.aligned.m8n8.x4.shared.b16 {%0,%1,%2,%3}, [%4];"
                    : "=r"(r0), "=r"(r1), "=r"(r2), "=r"(r3) : "r"(bBb + off));
                bfB[ntp*2+0][0] = r0; bfB[ntp*2+0][1] = r2;
                bfB[ntp*2+1][0] = r1; bfB[ntp*2+1][1] = r3;
                asm volatile("ldmatrix.sync.aligned.m8n8.x4.shared.b16 {%0,%1,%2,%3}, [%4];"
                    : "=r"(r0), "=r"(r1), "=r"(r2), "=r"(r3) : "r"(bSb + off));
                bfS[ntp*2+0][0] = r0; bfS[ntp*2+0][1] = r2;
                bfS[ntp*2+1][0] = r1; bfS[ntp*2+1][1] = r3;
            }
            #pragma unroll
            for (int mt = 0; mt < 2; mt++)
                #pragma unroll
                for (int nt = 0; nt < 4; nt++) {
                    asm volatile(
                        "mma.sync.aligned.m16n8k16.row.col.f32.bf16.bf16.f32 "
                        "{%0,%1,%2,%3}, {%4,%5,%6,%7}, {%8,%9}, {%0,%1,%2,%3};"
                        : "+f"(d[mt][nt][0]), "+f"(d[mt][nt][1]),
                          "+f"(d[mt][nt][2]), "+f"(d[mt][nt][3])
                        : "r"(afB[mt][0]), "r"(afB[mt][1]), "r"(afB[mt][2]), "r"(afB[mt][3]),
                          "r"(bfB[nt][0]), "r"(bfB[nt][1]));
                    asm volatile(
                        "mma.sync.aligned.m16n8k16.row.col.f32.bf16.bf16.f32 "
                        "{%0,%1,%2,%3}, {%4,%5,%6,%7}, {%8,%9}, {%0,%1,%2,%3};"
                        : "+f"(d[mt][nt][0]), "+f"(d[mt][nt][1]),
                          "+f"(d[mt][nt][2]), "+f"(d[mt][nt][3])
                        : "r"(afB[mt][0]), "r"(afB[mt][1]), "r"(afB[mt][2]), "r"(afB[mt][3]),
                          "r"(bfS[nt][0]), "r"(bfS[nt][1]));
                    asm volatile(
                        "mma.sync.aligned.m16n8k16.row.col.f32.bf16.bf16.f32 "
                        "{%0,%1,%2,%3}, {%4,%5,%6,%7}, {%8,%9}, {%0,%1,%2,%3};"
                        : "+f"(d[mt][nt][0]), "+f"(d[mt][nt][1]),
                          "+f"(d[mt][nt][2]), "+f"(d[mt][nt][3])
                        : "r"(afS[mt][0]), "r"(afS[mt][1]), "r"(afS[mt][2]), "r"(afS[mt][3]),
                          "r"(bfB[nt][0]), "r"(bfB[nt][1]));
                }
        }
        __syncthreads();
    }

    int g8  = lane >> 2;
    int tig = lane & 3;
    #pragma unroll
    for (int mt = 0; mt < 2; mt++) {
        int r0 = mBase + wm + mt*16 + g8;
        int r1 = r0 + 8;
        #pragma unroll
        for (int nt = 0; nt < 4; nt++) {
            int c0 = wn + nt*8 + 2*tig;
            float x0 = d[mt][nt][0] + sb_bias[c0];
            float x1 = d[mt][nt][1] + sb_bias[c0+1];
            float x2 = d[mt][nt][2] + sb_bias[c0];
            float x3 = d[mt][nt][3] + sb_bias[c0+1];
            if (MODE == 2) {
                x0 = (x0 > 0.f) ? x0 : (__expf(x0) - 1.f);
                x1 = (x1 > 0.f) ? x1 : (__expf(x1) - 1.f);
                x2 = (x2 > 0.f) ? x2 : (__expf(x2) - 1.f);
                x3 = (x3 > 0.f) ? x3 : (__expf(x3) - 1.f);
            }
            if (r0 < M) *(float2*)&g.C[(size_t)r0*DD + c0] = make_float2(x0, x1);
            if (r1 < M) *(float2*)&g.C[(size_t)r1*DD + c0] = make_float2(x2, x3);
        }
    }
}

// ---------------- final logits at target rows (beta computed inline) --------
__global__ __launch_bounds__(256)
void final_kernel(const float* __restrict__ st0, const float* __restrict__ st1,
                  const float* __restrict__ lW1, const float* __restrict__ lb1,
                  const int* __restrict__ tgt, float* __restrict__ out) {
    int t    = blockIdx.x;
    int col  = threadIdx.x >> 5;
    int lane = threadIdx.x & 31;
    int n = tgt[t];
    float s0 = g_s[0] * (1.f/(float)NTn);
    float s1 = g_s[1] * (1.f/(float)NTn);
    float mm = fmaxf(s0, s1);
    float e0 = expf(s0 - mm), e1 = expf(s1 - mm);
    float b0 = e0 / (e0 + e1), b1 = e1 / (e0 + e1);
    float acc = 0.f;
    for (int k = lane; k < HDIM; k += 32) {
        float a = b0*st0[(size_t)n*HDIM + k] + b1*st1[(size_t)n*HDIM + k];
        acc += a * lW1[(size_t)k*COUT + col];
    }
    #pragma unroll
    for (int o = 16; o > 0; o >>= 1) acc += __shfl_xor_sync(0xffffffffu, acc, o);
    if (lane == 0) out[(size_t)t*COUT + col] = acc + lb1[col];
}

// ---------------- host orchestration ----------------
extern "C" void kernel_launch(void* const* d_in, const int* in_sizes, int n_in,
                              void* d_out, int out_size) {
    const float* X0   = (const float*)d_in[0];
    const float* X1   = (const float*)d_in[1];
    const float* X2   = (const float*)d_in[2];
    const float* fcW[3] = {(const float*)d_in[3], (const float*)d_in[5], (const float*)d_in[7]};
    const float* fcb[3] = {(const float*)d_in[4], (const float*)d_in[6], (const float*)d_in[8]};
    const float* attn1 = (const float*)d_in[9];
    const float* attn2 = (const float*)d_in[10];
    const float* mpW   = (const float*)d_in[11];
    const float* mpb   = (const float*)d_in[12];
    const float* mpq   = (const float*)d_in[13];
    const float* lW0   = (const float*)d_in[14];
    const float* lb0   = (const float*)d_in[15];
    const float* lW1   = (const float*)d_in[16];
    const float* lb1   = (const float*)d_in[17];
    const int*   mpidx = (const int*)d_in[18];
    const int*   tgt   = (const int*)d_in[19];
    float* out = (float*)d_out;

    float *h0, *h1, *stb, *sp;
    __nv_bfloat16 *btp, *wbp, *wsp;
    int *cnt, *ofs, *cur;
    cudaGetSymbolAddress((void**)&h0,  g_h0);
    cudaGetSymbolAddress((void**)&h1,  g_h1);
    cudaGetSymbolAddress((void**)&stb, g_st);
    cudaGetSymbolAddress((void**)&sp,  g_s);
    cudaGetSymbolAddress((void**)&cnt, g_counts);
    cudaGetSymbolAddress((void**)&ofs, g_ofs);
    cudaGetSymbolAddress((void**)&cur, g_cursor);
    cudaGetSymbolAddress((void**)&btp, g_bt);
    cudaGetSymbolAddress((void**)&wbp, g_wb);
    cudaGetSymbolAddress((void**)&wsp, g_ws);

    const size_t SLABST = (size_t)NTn*HDIM;
    const int mTiles = (NTn + 127) / 128;

    // 1-4: CSR build (hist needs counts zeroed)
    zero_i_kernel<<<(NSLAB*NTn + 255)/256, 256>>>(cnt, NSLAB*NTn);
    hist_kernel   <<<dim3((ECNT+255)/256, 1, NSLAB), 256>>>(mpidx, cnt);
    scan_kernel   <<<NSLAB, 1024>>>(cnt, ofs, cur);
    scatter_kernel<<<dim3((ECNT+255)/256, 1, NSLAB), 256>>>(mpidx, cur);

    // 5: split-transpose fc/layer weights
    {
        PArgs4 pa = {};
        pa.z[0] = {fcW[0], 512, WOFF0};
        pa.z[1] = {fcW[1], 256, WOFF1};
        pa.z[2] = {fcW[2], 128, WOFF2};
        pa.z[3] = {lW0,    512, WOFF3};
        prepW_kernel<<<dim3((64*512 + 255)/256, 1, 4), 256>>>(pa);
    }

    // 6: feature FC -> h0 (captured by ncu -s 5 -c 1)
    {
        HArgsN ga = {};
        const float* Xs[3] = {X0, X1, X2};
        const int    Ks[3] = {512, 256, 128};
        const int    Wo[3] = {WOFF0, WOFF1, WOFF2};
        for (int i = 0; i < NTYPES; i++) {
            ga.z[i].A0 = Xs[i];
            ga.z[i].Bb = wbp + Wo[i]; ga.z[i].Bs2 = wsp + Wo[i];
            ga.z[i].bias = fcb[i];
            ga.z[i].C = h0 + (size_t)i*NTn*DD;
            ga.z[i].K = Ks[i];
        }
        hgemm_kernel<0><<<dim3(mTiles, 1, NTYPES), 256>>>(NTn, ga);
    }

    // 7: mpW transpose (bf16)
    transW_kernel<<<dim3((AVd*HDIM+255)/256, 1, NTYPES+1), 256>>>(mpW);

    for (int l = 0; l < 2; l++) {
        const float* hin = (l == 0) ? h0 : h1;
        int nslab  = (l == 0) ? NSLAB : NMP;
        int ntypes = (l == 0) ? NTYPES : 1;

        dot_kernel <<<dim3((NNODES+7)/8, 1, ntypes), 256>>>(hin, attn1, attn2, l*NSLAB);
        edge_kernel<<<dim3((ECNT+255)/256, 1, nslab), 256>>>();
        node_kernel<<<dim3((NTn+7)/8, 1, nslab), 256>>>(hin);

        {
            T1ArgsN ga = {};
            for (int zz = 0; zz < nslab; zz++) {
                int type = (l == 0) ? (zz / NMP) : 0;
                int mi = (l == 0) ? type : NTYPES;
                int bi = l*NTYPES + type;
                ga.z[zz].A    = stb + (size_t)zz*SLABST;
                ga.z[zz].Bt   = btp + (size_t)mi*AVd*HDIM;
                ga.z[zz].bias = mpb + (size_t)bi*AVd;
                ga.z[zz].q    = mpq + (size_t)bi*AVd;
                ga.z[zz].sOut = sp + zz;
            }
            mp_attn_kernel<<<dim3(mTiles, 1, nslab), 256>>>(NTn, ga);
        }

        if (l == 0) {
            HArgsN ga = {};
            for (int t = 0; t < NTYPES; t++) {
                ga.z[t].A0 = stb + (size_t)(t*2+0)*SLABST;
                ga.z[t].A1 = stb + (size_t)(t*2+1)*SLABST;
                ga.z[t].Bb = wbp + WOFF3; ga.z[t].Bs2 = wsp + WOFF3;
                ga.z[t].bias = lb0;
                ga.z[t].C = h1 + (size_t)t*NTn*DD;
                ga.z[t].K = HDIM;
                ga.z[t].sIdx = t*2;
            }
            hgemm_kernel<2><<<dim3(mTiles, 1, NTYPES), 256>>>(NTn, ga);
        } else {
            final_kernel<<<NTGTn, 256>>>(stb, stb + SLABST, lW1, lb1, tgt, out);
        }
    }
}

// round 7
// speedup vs baseline: 2.7805x; 1.1036x over previous
#include <cuda_runtime.h>
#include <cuda_bf16.h>
#include <math.h>
#include <stdint.h>

#define NTn     34000
#define NTYPES  3
#define NMP     2
#define ECNT    300000
#define HH      8
#define DD      64
#define HDIM    512
#define AVd     128
#define COUT    8
#define NTGTn   1000
#define NNODES  (NTYPES*NTn)
#define NSLAB   (NTYPES*NMP)

// ---------------- scratch (device globals; no allocation) ----------------
__device__ float g_h0[(size_t)NNODES*DD];
__device__ float g_h1[(size_t)NNODES*DD];
__device__ float g_st[(size_t)NSLAB*NTn*HDIM];
__device__ float g_u [(size_t)NSLAB*NTn*HH];
__device__ float g_t2[(size_t)NSLAB*NNODES*HH];
__device__ int4  g_srt[(size_t)NSLAB*ECNT];
__device__ int   g_counts[NSLAB*NTn];
__device__ int   g_ofs   [NSLAB*NTn];
__device__ int   g_cursor[NSLAB*NTn];
__device__ float g_s[NSLAB];
__device__ __nv_bfloat16 g_bt[(size_t)(NTYPES+1)*AVd*HDIM];  // mpW^T bf16
// split-bf16 transposed weights [64][K]: fc0(K512), fc1(K256), fc2(K128), lW0(K512)
#define WOFF0 0
#define WOFF1 (64*512)
#define WOFF2 (WOFF1 + 64*256)
#define WOFF3 (WOFF2 + 64*128)
#define WTOT  (WOFF3 + 64*512)
__device__ __nv_bfloat16 g_wb[WTOT];
__device__ __nv_bfloat16 g_ws[WTOT];

__device__ __forceinline__ float tanh_apx(float x) {
    float y; asm("tanh.approx.f32 %0, %1;" : "=f"(y) : "f"(x)); return y;
}
__device__ __forceinline__ uint32_t smem_u32(const void* p) {
    uint32_t a;
    asm("{ .reg .u64 t; cvta.to.shared.u64 t, %1; cvt.u32.u64 %0, t; }"
        : "=r"(a) : "l"(p));
    return a;
}

// ---------------- small utility kernels ----------------
__global__ void zero_i_kernel(int* p, int n) {
    int i = blockIdx.x*blockDim.x + threadIdx.x;
    if (i < n) p[i] = 0;
}
// transpose mpW [mi][HDIM][AVd] -> bf16 [mi][AVd][HDIM]
__global__ void transW_kernel(const float* __restrict__ mpW) {
    int mi = blockIdx.z;
    int t = blockIdx.x*256 + threadIdx.x;
    if (t < AVd*HDIM) {
        int n = t >> 9;
        int k = t & 511;
        float v = mpW[(size_t)mi*HDIM*AVd + (size_t)k*AVd + n];
        g_bt[(size_t)mi*AVd*HDIM + (size_t)n*HDIM + k] = __float2bfloat16(v);
    }
}
// split-transpose W [K][64] -> big/small bf16 [64][K]
struct PArgs { const float* W; int K; int off; };
struct PArgs4 { PArgs z[4]; };
__global__ void prepW_kernel(PArgs4 pa) {
    PArgs g = pa.z[blockIdx.z];
    int idx = blockIdx.x*256 + threadIdx.x;
    if (idx < 64*g.K) {
        int n = idx & 63;
        int k = idx >> 6;
        float v = g.W[(size_t)k*64 + n];
        __nv_bfloat16 big = __float2bfloat16_rn(v);
        float r = v - __bfloat162float(big);
        g_wb[g.off + (size_t)n*g.K + k] = big;
        g_ws[g.off + (size_t)n*g.K + k] = __float2bfloat16_rn(r);
    }
}

// ---------------- CSR construction ----------------
__global__ void hist_kernel(const int* __restrict__ mpidx, int* __restrict__ counts) {
    int slab = blockIdx.z;
    int e = blockIdx.x*blockDim.x + threadIdx.x;
    if (e < ECNT) {
        int dst = mpidx[(size_t)slab*ECNT*3 + e*3] - (slab/NMP)*NTn;
        atomicAdd(&counts[(size_t)slab*NTn + dst], 1);
    }
}

__global__ void scan_kernel(const int* __restrict__ countsAll,
                            int* __restrict__ ofsAll, int* __restrict__ cursorAll) {
    int slab = blockIdx.x;
    const int4* counts4 = (const int4*)(countsAll + (size_t)slab*NTn);
    int4* ofs4    = (int4*)(ofsAll    + (size_t)slab*NTn);
    int4* cursor4 = (int4*)(cursorAll + (size_t)slab*NTn);
    const int N4 = NTn/4;
    __shared__ int warp_sums[32];
    __shared__ int s_carry;
    if (threadIdx.x == 0) s_carry = 0;
    __syncthreads();
    int lane = threadIdx.x & 31, wid = threadIdx.x >> 5;
    for (int base = 0; base < N4; base += 1024) {
        int i4 = base + threadIdx.x;
        int4 v = (i4 < N4) ? counts4[i4] : make_int4(0,0,0,0);
        int c1 = v.x, c2 = c1 + v.y, c3 = c2 + v.z, c4 = c3 + v.w;
        int tot = c4;
        int incl = tot;
        #pragma unroll
        for (int d = 1; d < 32; d <<= 1) {
            int t = __shfl_up_sync(0xffffffffu, incl, d);
            if (lane >= d) incl += t;
        }
        if (lane == 31) warp_sums[wid] = incl;
        __syncthreads();
        if (wid == 0) {
            int w = warp_sums[lane];
            #pragma unroll
            for (int d = 1; d < 32; d <<= 1) {
                int t = __shfl_up_sync(0xffffffffu, w, d);
                if (lane >= d) w += t;
            }
            warp_sums[lane] = w;
        }
        __syncthreads();
        int add = s_carry + (wid > 0 ? warp_sums[wid-1] : 0);
        int be  = add + incl - tot;
        if (i4 < N4) {
            int4 o = make_int4(be, be + c1, be + c2, be + c3);
            ofs4[i4] = o;
            cursor4[i4] = o;
        }
        __syncthreads();
        if (threadIdx.x == 1023) s_carry = add + incl;
        __syncthreads();
    }
}

__global__ void scatter_kernel(const int* __restrict__ mpidx, int* __restrict__ cursorAll) {
    int slab = blockIdx.z;
    int e = blockIdx.x*blockDim.x + threadIdx.x;
    if (e < ECNT) {
        const int* mp = mpidx + (size_t)slab*ECNT*3 + (size_t)e*3;
        int n0 = mp[0], n1 = mp[1], n2 = mp[2];
        int dst = n0 - (slab/NMP)*NTn;
        int pos = atomicAdd(&cursorAll[(size_t)slab*NTn + dst], 1);
        g_srt[(size_t)slab*ECNT + pos] = make_int4(n0, n1, n2, 0);
    }
}

// ---------------- per-node attention dots (warp/node, both metapaths of a type) ----
__global__ __launch_bounds__(256)
void dot_kernel(const float* __restrict__ h, const float* __restrict__ attn1,
                const float* __restrict__ attn2, int layerOff) {
    int type = blockIdx.z;
    size_t base = (size_t)(layerOff + type*NMP)*HH*DD;
    __shared__ float a1s[NMP*HH*DD];
    __shared__ float a2s[NMP*HH*DD];
    for (int i = threadIdx.x; i < NMP*HH*DD; i += blockDim.x) {
        a1s[i] = attn1[base + i];
        a2s[i] = attn2[base + i];
    }
    if (blockIdx.x == 0 && blockIdx.z == 0 && threadIdx.x < NSLAB)
        g_s[threadIdx.x] = 0.f;
    __syncthreads();
    int lane = threadIdx.x & 31;
    int wid  = threadIdx.x >> 5;
    int gn = blockIdx.x*8 + wid;
    if (gn >= NNODES) return;

    float hv0 = h[(size_t)gn*DD + lane];
    float hv1 = h[(size_t)gn*DD + 32 + lane];
    int ibase = type*NTn;
    bool isdst = (gn >= ibase) && (gn < ibase + NTn);
    const float third = 1.f/3.f;

    #pragma unroll
    for (int p = 0; p < NMP; p++) {
        int slab = type*NMP + p;
        const float* a2p = a2s + p*HH*DD;
        const float* a1p = a1s + p*HH*DD;
        float r2[HH], r1[HH];
        #pragma unroll
        for (int hh = 0; hh < HH; hh++) {
            float v = hv0*a2p[hh*DD+lane] + hv1*a2p[hh*DD+32+lane];
            #pragma unroll
            for (int o = 16; o > 0; o >>= 1) v += __shfl_xor_sync(0xffffffffu, v, o);
            r2[hh] = v;
        }
        if (isdst) {
            #pragma unroll
            for (int hh = 0; hh < HH; hh++) {
                float v = hv0*a1p[hh*DD+lane] + hv1*a1p[hh*DD+32+lane];
                #pragma unroll
                for (int o = 16; o > 0; o >>= 1) v += __shfl_xor_sync(0xffffffffu, v, o);
                r1[hh] = v;
            }
        }
        float myt2 = 0.f, myu = 0.f;
        #pragma unroll
        for (int hh = 0; hh < HH; hh++) {
            if (lane == hh) {
                myt2 = r2[hh];
                if (isdst) myu = r1[hh] + r2[hh]*third;
            }
        }
        if (lane < HH) {
            g_t2[((size_t)slab*NNODES + gn)*HH + lane] = myt2;
            if (isdst) g_u[((size_t)slab*NTn + (gn - ibase))*HH + lane] = myu;
        }
    }
}

// ---------------- fused logits + segment softmax + weighted sum (warp/node) -----
// ex computed inline from u/t2 tables (exp without max subtraction: |e| << 88).
__global__ __launch_bounds__(256)
void node_kernel(const float* __restrict__ h) {
    int slab = blockIdx.z;
    const int*  ofs = g_ofs + (size_t)slab*NTn;
    const int4* srt = g_srt + (size_t)slab*ECNT;
    const float* t2b = g_t2 + (size_t)slab*NNODES*HH;
    const float* ub  = g_u  + (size_t)slab*NTn*HH;
    float* st = g_st + (size_t)slab*NTn*HDIM;

    int lane = threadIdx.x & 31;
    int wid  = threadIdx.x >> 5;
    int n = blockIdx.x*8 + wid;
    if (n >= NTn) return;

    int s0 = ofs[n];
    int s1 = (n < NTn-1) ? ofs[n+1] : ECNT;
    if (s1 == s0) {   // empty segment -> st row = elu(0) = 0
        #pragma unroll
        for (int hh = 0; hh < HH; hh++) {
            st[(size_t)n*HDIM + hh*DD + lane]      = 0.f;
            st[(size_t)n*HDIM + hh*DD + 32 + lane] = 0.f;
        }
        return;
    }
    int ibase = (slab/NMP)*NTn;

    const int h_my = lane & 7;    // head handled by this lane for ex
    const int c_my = lane >> 3;   // chunk-slot handled by this lane for ex
    float u_my = ub[(size_t)n*HH + h_my];
    const float third = 1.f/3.f;

    float den_l = 0.f;
    float acc[2*HH];
    #pragma unroll
    for (int k = 0; k < 2*HH; k++) acc[k] = 0.f;

    for (int j = s0; j < s1; j += 4) {
        int m = s1 - j; if (m > 4) m = 4;
        int nn1[4], nn2[4];
        #pragma unroll
        for (int c = 0; c < 4; c++) {
            int jj = j + ((c < m) ? c : 0);
            int4 tr = srt[jj];
            nn1[c] = tr.y; nn2[c] = tr.z;
        }
        // ex for my (chunk-slot, head): one warp-wide load pass covers all 32
        float ta = t2b[(size_t)nn1[c_my]*HH + h_my];
        float tb = t2b[(size_t)nn2[c_my]*HH + h_my];
        float ev = u_my + (ta + tb)*third;
        ev = (ev > 0.f) ? ev : 0.2f*ev;          // leaky_relu 0.2
        float ex = (c_my < m) ? __expf(ev) : 0.f;
        den_l += ex;
        // mid-node feature gathers (all lanes, dims lane and lane+32)
        float f1a[4], f1b[4], f2a[4], f2b[4];
        #pragma unroll
        for (int c = 0; c < 4; c++) {
            f1a[c] = h[(size_t)nn1[c]*DD + lane];
            f1b[c] = h[(size_t)nn1[c]*DD + 32 + lane];
            f2a[c] = h[(size_t)nn2[c]*DD + lane];
            f2b[c] = h[(size_t)nn2[c]*DD + 32 + lane];
        }
        #pragma unroll
        for (int c = 0; c < 4; c++) {
            float sa = f1a[c] + f2a[c];
            float sb = f1b[c] + f2b[c];
            #pragma unroll
            for (int hh = 0; hh < HH; hh++) {
                float exh = __shfl_sync(0xffffffffu, ex, c*8 + hh);
                acc[hh*2+0] += exh * sa;
                acc[hh*2+1] += exh * sb;
            }
        }
    }

    // den: sum over chunk-slot groups (bits 3,4 of lane); head preserved
    den_l += __shfl_xor_sync(0xffffffffu, den_l, 8);
    den_l += __shfl_xor_sync(0xffffffffu, den_l, 16);

    float hn0a = h[(size_t)(ibase+n)*DD + lane];
    float hn0b = h[(size_t)(ibase+n)*DD + 32 + lane];
    #pragma unroll
    for (int hh = 0; hh < HH; hh++) {
        float dh = __shfl_sync(0xffffffffu, den_l, hh);  // lane hh holds head hh
        float inv = 1.f / dh;
        float v0 = (hn0a + acc[hh*2+0]*inv) * third;
        float v1 = (hn0b + acc[hh*2+1]*inv) * third;
        v0 = (v0 > 0.f) ? v0 : (__expf(v0) - 1.f);
        v1 = (v1 > 0.f) ? v1 : (__expf(v1) - 1.f);
        st[(size_t)n*HDIM + hh*DD + lane]      = v0;
        st[(size_t)n*HDIM + hh*DD + 32 + lane] = v1;
    }
}

// ---------------- HMMA bf16 mode-1 GEMM: s += sum_rows(tanh(A@B^T + bias).q) ----
struct T1Args { const float* A; const __nv_bfloat16* Bt;
                const float* bias; const float* q; float* sOut; };
struct T1ArgsN { T1Args z[NSLAB]; };

__global__ __launch_bounds__(256)
void mp_attn_kernel(int M, T1ArgsN ga) {
    constexpr int AP = 72;
    __shared__ __align__(16) __nv_bfloat16 As[128*AP];
    __shared__ __align__(16) __nv_bfloat16 Bs[128*AP];
    __shared__ float sb_bias[128], sb_q[128];
    __shared__ float red[256];
    const T1Args g = ga.z[blockIdx.z];
    const int tid  = threadIdx.x;
    const int wid  = tid >> 5;
    const int lane = tid & 31;
    const int mBase = blockIdx.x * 128;
    const int wm = (wid >> 2) * 64;
    const int wn = (wid & 3) * 32;

    if (tid < 128) { sb_bias[tid] = g.bias[tid]; sb_q[tid] = g.q[tid]; }

    float d[4][4][4];
    #pragma unroll
    for (int mt = 0; mt < 4; mt++)
        #pragma unroll
        for (int nt = 0; nt < 4; nt++)
            #pragma unroll
            for (int f = 0; f < 4; f++) d[mt][nt][f] = 0.f;

    float4 ra[8]; uint4 rb[4];
    int aRow[8], aCol[8], bRow[4], bCol[4];
    #pragma unroll
    for (int i = 0; i < 8; i++) {
        int t = tid + i*256;
        aRow[i] = t >> 4;
        aCol[i] = (t & 15) * 4;
    }
    #pragma unroll
    for (int i = 0; i < 4; i++) {
        int t = tid + i*256;
        bRow[i] = t >> 3;
        bCol[i] = (t & 7) * 8;
    }

    auto loadRegs = [&](int c) {
        #pragma unroll
        for (int i = 0; i < 8; i++) {
            int gr = mBase + aRow[i];
            ra[i] = (gr < M)
                ? *(const float4*)(g.A + (size_t)gr*HDIM + c*64 + aCol[i])
                : make_float4(0.f, 0.f, 0.f, 0.f);
        }
        #pragma unroll
        for (int i = 0; i < 4; i++)
            rb[i] = *(const uint4*)(g.Bt + (size_t)bRow[i]*HDIM + c*64 + bCol[i]);
    };
    auto storeSmem = [&]() {
        #pragma unroll
        for (int i = 0; i < 8; i++) {
            __nv_bfloat162 p0 = __floats2bfloat162_rn(ra[i].x, ra[i].y);
            __nv_bfloat162 p1 = __floats2bfloat162_rn(ra[i].z, ra[i].w);
            uint2 u;
            u.x = *(uint32_t*)&p0;
            u.y = *(uint32_t*)&p1;
            *(uint2*)&As[aRow[i]*AP + aCol[i]] = u;
        }
        #pragma unroll
        for (int i = 0; i < 4; i++)
            *(uint4*)&Bs[bRow[i]*AP + bCol[i]] = rb[i];
    };

    uint32_t aSb = smem_u32(As);
    uint32_t bSb = smem_u32(Bs);

    loadRegs(0);
    #pragma unroll 1
    for (int c = 0; c < 8; c++) {
        storeSmem();
        __syncthreads();
        if (c < 7) loadRegs(c + 1);
        #pragma unroll
        for (int ks = 0; ks < 4; ks++) {
            uint32_t af[4][4];
            #pragma unroll
            for (int mt = 0; mt < 4; mt++) {
                uint32_t addr = aSb +
                    (((wm + mt*16 + (lane & 15))*AP + ks*16 + (lane >> 4)*8) << 1);
                asm volatile("ldmatrix.sync.aligned.m8n8.x4.shared.b16 {%0,%1,%2,%3}, [%4];"
                    : "=r"(af[mt][0]), "=r"(af[mt][1]), "=r"(af[mt][2]), "=r"(af[mt][3])
                    : "r"(addr));
            }
            uint32_t bf[4][2];
            #pragma unroll
            for (int nt = 0; nt < 4; nt++) {
                uint32_t addr = bSb +
                    (((wn + nt*8 + (lane & 7))*AP + ks*16 + ((lane >> 3) & 1)*8) << 1);
                asm volatile("ldmatrix.sync.aligned.m8n8.x2.shared.b16 {%0,%1}, [%2];"
                    : "=r"(bf[nt][0]), "=r"(bf[nt][1])
                    : "r"(addr));
            }
            #pragma unroll
            for (int mt = 0; mt < 4; mt++)
                #pragma unroll
                for (int nt = 0; nt < 4; nt++)
                    asm volatile(
                        "mma.sync.aligned.m16n8k16.row.col.f32.bf16.bf16.f32 "
                        "{%0,%1,%2,%3}, {%4,%5,%6,%7}, {%8,%9}, {%0,%1,%2,%3};"
                        : "+f"(d[mt][nt][0]), "+f"(d[mt][nt][1]),
                          "+f"(d[mt][nt][2]), "+f"(d[mt][nt][3])
                        : "r"(af[mt][0]), "r"(af[mt][1]), "r"(af[mt][2]), "r"(af[mt][3]),
                          "r"(bf[nt][0]), "r"(bf[nt][1]));
        }
        __syncthreads();
    }

    int g8  = lane >> 2;
    int tig = lane & 3;
    float local = 0.f;
    #pragma unroll
    for (int mt = 0; mt < 4; mt++) {
        int r0 = mBase + wm + mt*16 + g8;
        int r1 = r0 + 8;
        #pragma unroll
        for (int nt = 0; nt < 4; nt++) {
            int c0 = wn + nt*8 + 2*tig;
            float b0v = sb_bias[c0],   q0v = sb_q[c0];
            float b1v = sb_bias[c0+1], q1v = sb_q[c0+1];
            if (r0 < M)
                local += tanh_apx(d[mt][nt][0] + b0v)*q0v
                       + tanh_apx(d[mt][nt][1] + b1v)*q1v;
            if (r1 < M)
                local += tanh_apx(d[mt][nt][2] + b0v)*q0v
                       + tanh_apx(d[mt][nt][3] + b1v)*q1v;
        }
    }
    red[tid] = local;
    __syncthreads();
    if (tid < 128) red[tid] += red[tid + 128];
    __syncthreads();
    if (tid < 64) red[tid] += red[tid + 64];
    __syncthreads();
    if (tid < 32) {
        float v = red[tid] + red[tid + 32];
        #pragma unroll
        for (int o = 16; o > 0; o >>= 1) v += __shfl_xor_sync(0xffffffffu, v, o);
        if (tid == 0) atomicAdd(g.sOut, v);
    }
}

// ---------------- split-bf16 HMMA GEMM (exact-ish fp32): N=64 ----------------
struct HArgs { const float* A0; const float* A1;
               const __nv_bfloat16* Bb; const __nv_bfloat16* Bs2;
               const float* bias; float* C; int K; int sIdx; };
struct HArgsN { HArgs z[NTYPES]; };

template<int MODE>
__global__ __launch_bounds__(256)
void hgemm_kernel(int M, HArgsN ga) {
    constexpr int AP = 72;
    __shared__ __align__(16) __nv_bfloat16 AsB[128*AP];
    __shared__ __align__(16) __nv_bfloat16 AsS[128*AP];
    __shared__ __align__(16) __nv_bfloat16 BsB[64*AP];
    __shared__ __align__(16) __nv_bfloat16 BsS[64*AP];
    __shared__ float sb_bias[64];
    __shared__ float sb_beta[2];
    const HArgs g = ga.z[blockIdx.z];
    const int tid  = threadIdx.x;
    const int wid  = tid >> 5;
    const int lane = tid & 31;
    const int mBase = blockIdx.x * 128;
    const int wm = (wid >> 1) * 32;
    const int wn = (wid & 1) * 32;
    const int K = g.K;

    if (tid < 64) sb_bias[tid] = g.bias[tid];
    if (MODE == 2 && tid == 0) {
        float s0 = g_s[g.sIdx]   * (1.f/(float)NTn);
        float s1 = g_s[g.sIdx+1] * (1.f/(float)NTn);
        float mm = fmaxf(s0, s1);
        float e0 = expf(s0 - mm), e1 = expf(s1 - mm);
        sb_beta[0] = e0 / (e0 + e1);
        sb_beta[1] = e1 / (e0 + e1);
    }
    __syncthreads();
    float cb0 = 0.f, cb1 = 0.f;
    if (MODE == 2) { cb0 = sb_beta[0]; cb1 = sb_beta[1]; }

    float d[2][4][4];
    #pragma unroll
    for (int mt = 0; mt < 2; mt++)
        #pragma unroll
        for (int nt = 0; nt < 4; nt++)
            #pragma unroll
            for (int f = 0; f < 4; f++) d[mt][nt][f] = 0.f;

    float4 ra0[8], ra1[8]; uint4 rbb[2], rbs[2];
    int aRow[8], aCol[8], bRow[2], bCol[2];
    #pragma unroll
    for (int i = 0; i < 8; i++) {
        int t = tid + i*256;
        aRow[i] = t >> 4;
        aCol[i] = (t & 15) * 4;
    }
    #pragma unroll
    for (int i = 0; i < 2; i++) {
        int t = tid + i*256;
        bRow[i] = t >> 3;
        bCol[i] = (t & 7) * 8;
    }

    auto loadRegs = [&](int c) {
        #pragma unroll
        for (int i = 0; i < 8; i++) {
            int gr = mBase + aRow[i];
            float4 v = make_float4(0.f,0.f,0.f,0.f);
            float4 w = make_float4(0.f,0.f,0.f,0.f);
            if (gr < M) {
                v = *(const float4*)(g.A0 + (size_t)gr*K + c*64 + aCol[i]);
                if (MODE == 2)
                    w = *(const float4*)(g.A1 + (size_t)gr*K + c*64 + aCol[i]);
            }
            ra0[i] = v;
            if (MODE == 2) ra1[i] = w;
        }
        #pragma unroll
        for (int i = 0; i < 2; i++) {
            rbb[i] = *(const uint4*)(g.Bb  + (size_t)bRow[i]*K + c*64 + bCol[i]);
            rbs[i] = *(const uint4*)(g.Bs2 + (size_t)bRow[i]*K + c*64 + bCol[i]);
        }
    };
    auto storeSmem = [&]() {
        #pragma unroll
        for (int i = 0; i < 8; i++) {
            float4 v = ra0[i];
            if (MODE == 2) {
                float4 w = ra1[i];
                v.x = cb0*v.x + cb1*w.x;  v.y = cb0*v.y + cb1*w.y;
                v.z = cb0*v.z + cb1*w.z;  v.w = cb0*v.w + cb1*w.w;
            }
            __nv_bfloat16 bx = __float2bfloat16_rn(v.x);
            __nv_bfloat16 by = __float2bfloat16_rn(v.y);
            __nv_bfloat16 bz = __float2bfloat16_rn(v.z);
            __nv_bfloat16 bw = __float2bfloat16_rn(v.w);
            __nv_bfloat16 sx = __float2bfloat16_rn(v.x - __bfloat162float(bx));
            __nv_bfloat16 sy = __float2bfloat16_rn(v.y - __bfloat162float(by));
            __nv_bfloat16 sz = __float2bfloat16_rn(v.z - __bfloat162float(bz));
            __nv_bfloat16 sw = __float2bfloat16_rn(v.w - __bfloat162float(bw));
            __nv_bfloat162 pb0 = __halves2bfloat162(bx, by);
            __nv_bfloat162 pb1 = __halves2bfloat162(bz, bw);
            __nv_bfloat162 ps0 = __halves2bfloat162(sx, sy);
            __nv_bfloat162 ps1 = __halves2bfloat162(sz, sw);
            uint2 ub, us;
            ub.x = *(uint32_t*)&pb0;  ub.y = *(uint32_t*)&pb1;
            us.x = *(uint32_t*)&ps0;  us.y = *(uint32_t*)&ps1;
            *(uint2*)&AsB[aRow[i]*AP + aCol[i]] = ub;
            *(uint2*)&AsS[aRow[i]*AP + aCol[i]] = us;
        }
        #pragma unroll
        for (int i = 0; i < 2; i++) {
            *(uint4*)&BsB[bRow[i]*AP + bCol[i]] = rbb[i];
            *(uint4*)&BsS[bRow[i]*AP + bCol[i]] = rbs[i];
        }
    };

    uint32_t aBb = smem_u32(AsB), aSb = smem_u32(AsS);
    uint32_t bBb = smem_u32(BsB), bSb = smem_u32(BsS);

    const int chunks = K >> 6;
    loadRegs(0);
    #pragma unroll 1
    for (int c = 0; c < chunks; c++) {
        storeSmem();
        __syncthreads();
        if (c + 1 < chunks) loadRegs(c + 1);
        #pragma unroll
        for (int ks = 0; ks < 4; ks++) {
            uint32_t afB[2][4], afS[2][4];
            #pragma unroll
            for (int mt = 0; mt < 2; mt++) {
                uint32_t off = ((wm + mt*16 + (lane & 15))*AP + ks*16 + (lane >> 4)*8) << 1;
                asm volatile("ldmatrix.sync.aligned.m8n8.x4.shared.b16 {%0,%1,%2,%3}, [%4];"
                    : "=r"(afB[mt][0]), "=r"(afB[mt][1]), "=r"(afB[mt][2]), "=r"(afB[mt][3])
                    : "r"(aBb + off));
                asm volatile("ldmatrix.sync.aligned.m8n8.x4.shared.b16 {%0,%1,%2,%3}, [%4];"
                    : "=r"(afS[mt][0]), "=r"(afS[mt][1]), "=r"(afS[mt][2]), "=r"(afS[mt][3])
                    : "r"(aSb + off));
            }
            uint32_t bfB[4][2], bfS[4][2];
            #pragma unroll
            for (int ntp = 0; ntp < 2; ntp++) {
                uint32_t off = ((wn + ntp*16 + (lane & 15))*AP + ks*16 + (lane >> 4)*8) << 1;
                uint32_t r0, r1, r2, r3;
                asm volatile("ldmatrix.sync.aligned.m8n8.x4.shared.b16 {%0,%1,%2,%3}, [%4];"
                    : "=r"(r0), "=r"(r1), "=r"(r2), "=r"(r3) : "r"(bBb + off));
                bfB[ntp*2+0][0] = r0; bfB[ntp*2+0][1] = r2;
                bfB[ntp*2+1][0] = r1; bfB[ntp*2+1][1] = r3;
                asm volatile("ldmatrix.sync.aligned.m8n8.x4.shared.b16 {%0,%1,%2,%3}, [%4];"
                    : "=r"(r0), "=r"(r1), "=r"(r2), "=r"(r3) : "r"(bSb + off));
                bfS[ntp*2+0][0] = r0; bfS[ntp*2+0][1] = r2;
                bfS[ntp*2+1][0] = r1; bfS[ntp*2+1][1] = r3;
            }
            #pragma unroll
            for (int mt = 0; mt < 2; mt++)
                #pragma unroll
                for (int nt = 0; nt < 4; nt++) {
                    asm volatile(
                        "mma.sync.aligned.m16n8k16.row.col.f32.bf16.bf16.f32 "
                        "{%0,%1,%2,%3}, {%4,%5,%6,%7}, {%8,%9}, {%0,%1,%2,%3};"
                        : "+f"(d[mt][nt][0]), "+f"(d[mt][nt][1]),
                          "+f"(d[mt][nt][2]), "+f"(d[mt][nt][3])
                        : "r"(afB[mt][0]), "r"(afB[mt][1]), "r"(afB[mt][2]), "r"(afB[mt][3]),
                          "r"(bfB[nt][0]), "r"(bfB[nt][1]));
                    asm volatile(
                        "mma.sync.aligned.m16n8k16.row.col.f32.bf16.bf16.f32 "
                        "{%0,%1,%2,%3}, {%4,%5,%6,%7}, {%8,%9}, {%0,%1,%2,%3};"
                        : "+f"(d[mt][nt][0]), "+f"(d[mt][nt][1]),
                          "+f"(d[mt][nt][2]), "+f"(d[mt][nt][3])
                        : "r"(afB[mt][0]), "r"(afB[mt][1]), "r"(afB[mt][2]), "r"(afB[mt][3]),
                          "r"(bfS[nt][0]), "r"(bfS[nt][1]));
                    asm volatile(
                        "mma.sync.aligned.m16n8k16.row.col.f32.bf16.bf16.f32 "
                        "{%0,%1,%2,%3}, {%4,%5,%6,%7}, {%8,%9}, {%0,%1,%2,%3};"
                        : "+f"(d[mt][nt][0]), "+f"(d[mt][nt][1]),
                          "+f"(d[mt][nt][2]), "+f"(d[mt][nt][3])
                        : "r"(afS[mt][0]), "r"(afS[mt][1]), "r"(afS[mt][2]), "r"(afS[mt][3]),
                          "r"(bfB[nt][0]), "r"(bfB[nt][1]));
                }
        }
        __syncthreads();
    }

    int g8  = lane >> 2;
    int tig = lane & 3;
    #pragma unroll
    for (int mt = 0; mt < 2; mt++) {
        int r0 = mBase + wm + mt*16 + g8;
        int r1 = r0 + 8;
        #pragma unroll
        for (int nt = 0; nt < 4; nt++) {
            int c0 = wn + nt*8 + 2*tig;
            float x0 = d[mt][nt][0] + sb_bias[c0];
            float x1 = d[mt][nt][1] + sb_bias[c0+1];
            float x2 = d[mt][nt][2] + sb_bias[c0];
            float x3 = d[mt][nt][3] + sb_bias[c0+1];
            if (MODE == 2) {
                x0 = (x0 > 0.f) ? x0 : (__expf(x0) - 1.f);
                x1 = (x1 > 0.f) ? x1 : (__expf(x1) - 1.f);
                x2 = (x2 > 0.f) ? x2 : (__expf(x2) - 1.f);
                x3 = (x3 > 0.f) ? x3 : (__expf(x3) - 1.f);
            }
            if (r0 < M) *(float2*)&g.C[(size_t)r0*DD + c0] = make_float2(x0, x1);
            if (r1 < M) *(float2*)&g.C[(size_t)r1*DD + c0] = make_float2(x2, x3);
        }
    }
}

// ---------------- final logits at target rows (beta computed inline) --------
__global__ __launch_bounds__(256)
void final_kernel(const float* __restrict__ st0, const float* __restrict__ st1,
                  const float* __restrict__ lW1, const float* __restrict__ lb1,
                  const int* __restrict__ tgt, float* __restrict__ out) {
    int t    = blockIdx.x;
    int col  = threadIdx.x >> 5;
    int lane = threadIdx.x & 31;
    int n = tgt[t];
    float s0 = g_s[0] * (1.f/(float)NTn);
    float s1 = g_s[1] * (1.f/(float)NTn);
    float mm = fmaxf(s0, s1);
    float e0 = expf(s0 - mm), e1 = expf(s1 - mm);
    float b0 = e0 / (e0 + e1), b1 = e1 / (e0 + e1);
    float acc = 0.f;
    for (int k = lane; k < HDIM; k += 32) {
        float a = b0*st0[(size_t)n*HDIM + k] + b1*st1[(size_t)n*HDIM + k];
        acc += a * lW1[(size_t)k*COUT + col];
    }
    #pragma unroll
    for (int o = 16; o > 0; o >>= 1) acc += __shfl_xor_sync(0xffffffffu, acc, o);
    if (lane == 0) out[(size_t)t*COUT + col] = acc + lb1[col];
}

// ---------------- host orchestration ----------------
extern "C" void kernel_launch(void* const* d_in, const int* in_sizes, int n_in,
                              void* d_out, int out_size) {
    const float* X0   = (const float*)d_in[0];
    const float* X1   = (const float*)d_in[1];
    const float* X2   = (const float*)d_in[2];
    const float* fcW[3] = {(const float*)d_in[3], (const float*)d_in[5], (const float*)d_in[7]};
    const float* fcb[3] = {(const float*)d_in[4], (const float*)d_in[6], (const float*)d_in[8]};
    const float* attn1 = (const float*)d_in[9];
    const float* attn2 = (const float*)d_in[10];
    const float* mpW   = (const float*)d_in[11];
    const float* mpb   = (const float*)d_in[12];
    const float* mpq   = (const float*)d_in[13];
    const float* lW0   = (const float*)d_in[14];
    const float* lb0   = (const float*)d_in[15];
    const float* lW1   = (const float*)d_in[16];
    const float* lb1   = (const float*)d_in[17];
    const int*   mpidx = (const int*)d_in[18];
    const int*   tgt   = (const int*)d_in[19];
    float* out = (float*)d_out;

    float *h0, *h1, *stb, *sp;
    __nv_bfloat16 *btp, *wbp, *wsp;
    int *cnt, *ofs, *cur;
    cudaGetSymbolAddress((void**)&h0,  g_h0);
    cudaGetSymbolAddress((void**)&h1,  g_h1);
    cudaGetSymbolAddress((void**)&stb, g_st);
    cudaGetSymbolAddress((void**)&sp,  g_s);
    cudaGetSymbolAddress((void**)&cnt, g_counts);
    cudaGetSymbolAddress((void**)&ofs, g_ofs);
    cudaGetSymbolAddress((void**)&cur, g_cursor);
    cudaGetSymbolAddress((void**)&btp, g_bt);
    cudaGetSymbolAddress((void**)&wbp, g_wb);
    cudaGetSymbolAddress((void**)&wsp, g_ws);

    const size_t SLABST = (size_t)NTn*HDIM;
    const int mTiles = (NTn + 127) / 128;

    // CSR build
    zero_i_kernel<<<(NSLAB*NTn + 255)/256, 256>>>(cnt, NSLAB*NTn);
    hist_kernel   <<<dim3((ECNT+255)/256, 1, NSLAB), 256>>>(mpidx, cnt);
    scan_kernel   <<<NSLAB, 1024>>>(cnt, ofs, cur);
    scatter_kernel<<<dim3((ECNT+255)/256, 1, NSLAB), 256>>>(mpidx, cur);

    // split-transpose fc/layer weights
    {
        PArgs4 pa = {};
        pa.z[0] = {fcW[0], 512, WOFF0};
        pa.z[1] = {fcW[1], 256, WOFF1};
        pa.z[2] = {fcW[2], 128, WOFF2};
        pa.z[3] = {lW0,    512, WOFF3};
        prepW_kernel<<<dim3((64*512 + 255)/256, 1, 4), 256>>>(pa);
    }

    // feature FC -> h0
    {
        HArgsN ga = {};
        const float* Xs[3] = {X0, X1, X2};
        const int    Ks[3] = {512, 256, 128};
        const int    Wo[3] = {WOFF0, WOFF1, WOFF2};
        for (int i = 0; i < NTYPES; i++) {
            ga.z[i].A0 = Xs[i];
            ga.z[i].Bb = wbp + Wo[i]; ga.z[i].Bs2 = wsp + Wo[i];
            ga.z[i].bias = fcb[i];
            ga.z[i].C = h0 + (size_t)i*NTn*DD;
            ga.z[i].K = Ks[i];
        }
        hgemm_kernel<0><<<dim3(mTiles, 1, NTYPES), 256>>>(NTn, ga);
    }

    // mpW transpose (bf16)
    transW_kernel<<<dim3((AVd*HDIM+255)/256, 1, NTYPES+1), 256>>>(mpW);

    for (int l = 0; l < 2; l++) {
        const float* hin = (l == 0) ? h0 : h1;
        int nslab  = (l == 0) ? NSLAB : NMP;
        int ntypes = (l == 0) ? NTYPES : 1;

        dot_kernel <<<dim3((NNODES+7)/8, 1, ntypes), 256>>>(hin, attn1, attn2, l*NSLAB);
        node_kernel<<<dim3((NTn+7)/8, 1, nslab), 256>>>(hin);

        {
            T1ArgsN ga = {};
            for (int zz = 0; zz < nslab; zz++) {
                int type = (l == 0) ? (zz / NMP) : 0;
                int mi = (l == 0) ? type : NTYPES;
                int bi = l*NTYPES + type;
                ga.z[zz].A    = stb + (size_t)zz*SLABST;
                ga.z[zz].Bt   = btp + (size_t)mi*AVd*HDIM;
                ga.z[zz].bias = mpb + (size_t)bi*AVd;
                ga.z[zz].q    = mpq + (size_t)bi*AVd;
                ga.z[zz].sOut = sp + zz;
            }
            mp_attn_kernel<<<dim3(mTiles, 1, nslab), 256>>>(NTn, ga);
        }

        if (l == 0) {
            HArgsN ga = {};
            for (int t = 0; t < NTYPES; t++) {
                ga.z[t].A0 = stb + (size_t)(t*2+0)*SLABST;
                ga.z[t].A1 = stb + (size_t)(t*2+1)*SLABST;
                ga.z[t].Bb = wbp + WOFF3; ga.z[t].Bs2 = wsp + WOFF3;
                ga.z[t].bias = lb0;
                ga.z[t].C = h1 + (size_t)t*NTn*DD;
                ga.z[t].K = HDIM;
                ga.z[t].sIdx = t*2;
            }
            hgemm_kernel<2><<<dim3(mTiles, 1, NTYPES), 256>>>(NTn, ga);
        } else {
            final_kernel<<<NTGTn, 256>>>(stb, stb + SLABST, lW1, lb1, tgt, out);
        }
    }
}